// round 2
// baseline (speedup 1.0000x reference)
#include <cuda_runtime.h>
#include <math.h>

#define BT    3840
#define NROWS 76800

__device__ float g_tok [NROWS*32];
__device__ float g_qkv [NROWS*96];
__device__ float g_attn[NROWS*32];
__device__ float g_tok2[NROWS*32];
__device__ float g_hid [NROWS*128];
__device__ float g_hm  [BT*32];
__device__ float g_hcat[BT*32];

__constant__ unsigned c_maskb[20] = {
    0x1Fu,0x73u,0x1DDu,0x33Du,0x23Bu,0x67Au,0xC76u,0x3984u,0x779Cu,0xE738u,
    0x1CF70u,0x18CC0u,0x33180u,0x2F380u,0x6E700u,0x5EE00u,0x59C00u,0x67000u,0x7C000u,0xFFFFFu
};

// ---------------- CNN: conv1(s5)+relu+pool2 -> conv2(s2)+relu+pool2+mean, +pos_emb
// 8 samples/block (1 warp each), thread = output channel.
__global__ __launch_bounds__(256) void k_cnn(
    const float* __restrict__ x, const float* __restrict__ c1w, const float* __restrict__ c1b,
    const float* __restrict__ c2w, const float* __restrict__ c2b, const float* __restrict__ pos)
{
    __shared__ float w1s[160], b1s[32], w2s[5120], b2s[32], sx[1600], h1[5120];
    int tid = threadIdx.x, w = tid >> 5, oc = tid & 31;
    int n0 = blockIdx.x * 8;

    for (int i = tid; i < 160; i += 256) { int o = i/5, k = i%5; w1s[k*32+o] = c1w[i]; }
    if (tid < 32) { b1s[tid] = c1b[tid]; b2s[tid] = c2b[tid]; }
    for (int i = tid; i < 5120; i += 256) { int o = i/160, r = i%160, ic = r/5, k = r%5;
        w2s[(ic*5+k)*32+o] = c2w[i]; }
    const float4* xg = (const float4*)(x + (size_t)n0*200);
    float4* sx4 = (float4*)sx;
    for (int i = tid; i < 400; i += 256) sx4[i] = xg[i];
    __syncthreads();

    const float* xs = sx + w*200;
    float* h1s = h1 + w*640;
    float w1r[5];
    #pragma unroll
    for (int k = 0; k < 5; k++) w1r[k] = w1s[k*32+oc];
    float b1r = b1s[oc];
    #pragma unroll
    for (int j = 0; j < 20; j++) {
        float o0 = b1r, o1 = b1r;
        #pragma unroll
        for (int k = 0; k < 5; k++) { o0 += xs[10*j+k]*w1r[k]; o1 += xs[10*j+5+k]*w1r[k]; }
        h1s[j*32+oc] = fmaxf(fmaxf(o0,0.f), fmaxf(o1,0.f));
    }
    __syncthreads();

    float acc[8];
    #pragma unroll
    for (int j = 0; j < 8; j++) acc[j] = 0.f;
    #pragma unroll 4
    for (int ic = 0; ic < 32; ic++) {
        float inr[20];
        #pragma unroll
        for (int t = 0; t < 20; t++) inr[t] = h1s[t*32+ic];
        float wr[5];
        #pragma unroll
        for (int k = 0; k < 5; k++) wr[k] = w2s[(ic*5+k)*32+oc];
        #pragma unroll
        for (int j = 0; j < 8; j++) {
            #pragma unroll
            for (int k = 0; k < 5; k++) acc[j] += inr[2*j+k]*wr[k];
        }
    }
    int n = n0 + w, bt = n/19, c = n - bt*19;
    float b2r = b2s[oc], v = 0.f;
    #pragma unroll
    for (int u = 0; u < 4; u++)
        v += fmaxf(fmaxf(acc[2*u]+b2r,0.f), fmaxf(acc[2*u+1]+b2r,0.f));
    g_tok[((size_t)bt*20+c)*32+oc] = 0.25f*v + pos[c*32+oc];
}

__global__ void k_marker(const float* __restrict__ pos)
{
    int i = blockIdx.x*256 + threadIdx.x;
    if (i < BT*32) { int bt = i>>5, d = i&31; g_tok[((size_t)bt*20+19)*32+d] = pos[19*32+d]; }
}

// ---------------- QKV: [64 rows,32] x [32,96]+b ; thread = 2 rows x 12 cols
__global__ __launch_bounds__(256) void k_qkv(
    const float* __restrict__ wq, const float* __restrict__ bq,
    const float* __restrict__ wk, const float* __restrict__ bk,
    const float* __restrict__ wv, const float* __restrict__ bv)
{
    __shared__ float WT[3072], sb[96], As[64*33];
    int tid = threadIdx.x, r0 = blockIdx.x*64;
    for (int i = tid; i < 3072; i += 256) {
        int j = i/96, n = i%96;
        WT[i] = (n<32) ? wq[n*32+j] : (n<64) ? wk[(n-32)*32+j] : wv[(n-64)*32+j];
    }
    for (int i = tid; i < 96; i += 256) sb[i] = (i<32)?bq[i]:(i<64)?bk[i-32]:bv[i-64];
    for (int i = tid; i < 2048; i += 256) As[(i>>5)*33 + (i&31)] = g_tok[(size_t)r0*32 + i];
    __syncthreads();

    int rowg = tid>>3, colg = tid&7;
    float acc0[12], acc1[12];
    #pragma unroll
    for (int c = 0; c < 12; c++) { acc0[c]=0.f; acc1[c]=0.f; }
    #pragma unroll 8
    for (int j = 0; j < 32; j++) {
        float a0 = As[(2*rowg)*33+j], a1 = As[(2*rowg+1)*33+j];
        const float* wp = WT + j*96 + colg*12;
        #pragma unroll
        for (int c = 0; c < 12; c++) { float wv_ = wp[c]; acc0[c] += a0*wv_; acc1[c] += a1*wv_; }
    }
    #pragma unroll
    for (int c = 0; c < 12; c++) {
        float b = sb[colg*12+c];
        g_qkv[((size_t)r0+2*rowg)*96 + colg*12+c]   = acc0[c]+b;
        g_qkv[((size_t)r0+2*rowg+1)*96 + colg*12+c] = acc1[c]+b;
    }
}

// ---------------- attention per sample; thread = (t, head)
__global__ __launch_bounds__(160) void k_attn()
{
    __shared__ float qs[720], ks[720], vs[720], as_[160*21];
    int tid = threadIdx.x, bt = blockIdx.x;
    const float* base = g_qkv + (size_t)bt*1920;
    for (int i = tid; i < 1920; i += 160) {
        int t = i/96, c = i%96; float v = base[i];
        if (c<32) qs[t*36+c]=v; else if (c<64) ks[t*36+c-32]=v; else vs[t*36+c-64]=v;
    }
    __syncthreads();
    int t = tid>>3, h = tid&7;
    float4 q4 = *(const float4*)(qs + t*36 + h*4);
    unsigned mb = c_maskb[t];
    float sc[20], mx = -1e30f;
    #pragma unroll
    for (int kt = 0; kt < 20; kt++) {
        float4 k4 = *(const float4*)(ks + kt*36 + h*4);
        float s = 0.5f*(q4.x*k4.x+q4.y*k4.y+q4.z*k4.z+q4.w*k4.w);
        if (!((mb>>kt)&1u)) s = -1e9f;
        sc[kt] = s; mx = fmaxf(mx, s);
    }
    float sum = 0.f;
    #pragma unroll
    for (int kt = 0; kt < 20; kt++) { sc[kt] = expf(sc[kt]-mx); sum += sc[kt]; }
    float inv = 1.f/sum;
    float* ar = as_ + tid*21;
    #pragma unroll
    for (int kt = 0; kt < 20; kt++) ar[kt] = sc[kt]*inv;
    __syncthreads();
    float4 o = make_float4(0.f,0.f,0.f,0.f);
    #pragma unroll
    for (int kt = 0; kt < 20; kt++) {
        float a = ar[kt];
        float4 v4 = *(const float4*)(vs + kt*36 + h*4);
        o.x += a*v4.x; o.y += a*v4.y; o.z += a*v4.z; o.w += a*v4.w;
    }
    *(float4*)(g_attn + ((size_t)bt*20+t)*32 + h*4) = o;
}

// ---------------- proj + residual + LN1 -> g_tok2 ; 64 rows/block
__global__ __launch_bounds__(256) void k_proj(
    const float* __restrict__ wo, const float* __restrict__ bo,
    const float* __restrict__ g1, const float* __restrict__ be1)
{
    __shared__ float WT[1024], As[64*33], Os[64*33], sb[32], sg[32], sbe[32], smu[64], srs[64];
    int tid = threadIdx.x, r0 = blockIdx.x*64;
    for (int i = tid; i < 1024; i += 256) { int d = i>>5, j = i&31; WT[j*32+d] = wo[i]; }
    if (tid < 32) { sb[tid]=bo[tid]; sg[tid]=g1[tid]; sbe[tid]=be1[tid]; }
    for (int i = tid; i < 2048; i += 256) As[(i>>5)*33+(i&31)] = g_attn[(size_t)r0*32+i];
    __syncthreads();

    int rowg = tid>>3, colg = tid&7;
    float4 a0 = make_float4(0,0,0,0), a1 = make_float4(0,0,0,0);
    #pragma unroll 8
    for (int j = 0; j < 32; j++) {
        float4 w4 = *(const float4*)(WT + j*32 + colg*4);
        float x0 = As[(2*rowg)*33+j], x1 = As[(2*rowg+1)*33+j];
        a0.x += x0*w4.x; a0.y += x0*w4.y; a0.z += x0*w4.z; a0.w += x0*w4.w;
        a1.x += x1*w4.x; a1.y += x1*w4.y; a1.z += x1*w4.z; a1.w += x1*w4.w;
    }
    float4 b4 = *(const float4*)(sb + colg*4);
    #pragma unroll
    for (int i = 0; i < 2; i++) {
        int rr = 2*rowg+i;
        float4 res = *(const float4*)(g_tok + ((size_t)r0+rr)*32 + colg*4);
        float4 ac = i ? a1 : a0;
        float* d = Os + rr*33 + colg*4;
        d[0]=ac.x+b4.x+res.x; d[1]=ac.y+b4.y+res.y; d[2]=ac.z+b4.z+res.z; d[3]=ac.w+b4.w+res.w;
    }
    __syncthreads();
    if (tid < 64) {
        const float* row = Os + tid*33;
        float mu = 0.f;
        #pragma unroll
        for (int j = 0; j < 32; j++) mu += row[j];
        mu *= 0.03125f;
        float var = 0.f;
        #pragma unroll
        for (int j = 0; j < 32; j++) { float dd = row[j]-mu; var += dd*dd; }
        smu[tid] = mu; srs[tid] = rsqrtf(var*0.03125f + 1e-5f);
    }
    __syncthreads();
    for (int i = tid; i < 2048; i += 256) {
        int rr = i>>5, d = i&31;
        g_tok2[(size_t)r0*32+i] = (Os[rr*33+d]-smu[rr])*srs[rr]*sg[d] + sbe[d];
    }
}

// ---------------- FF1: relu([64,32]x[32,128]+b) -> g_hid ; thread = 4 rows x 8 cols
__global__ __launch_bounds__(256) void k_ff1(
    const float* __restrict__ w1, const float* __restrict__ b1)
{
    __shared__ float W1T[4096], sb1[128], As[64*33];
    int tid = threadIdx.x, r0 = blockIdx.x*64;
    for (int i = tid; i < 4096; i += 256) { int f = i>>5, j = i&31; W1T[j*128+f] = w1[i]; }
    if (tid < 128) sb1[tid] = b1[tid];
    for (int i = tid; i < 2048; i += 256) As[(i>>5)*33+(i&31)] = g_tok2[(size_t)r0*32+i];
    __syncthreads();

    int rowg = tid>>4, colg = tid&15;
    float acc[4][8];
    #pragma unroll
    for (int i = 0; i < 4; i++)
        #pragma unroll
        for (int c = 0; c < 8; c++) acc[i][c] = 0.f;
    #pragma unroll 4
    for (int j = 0; j < 32; j++) {
        const float* wp = W1T + j*128 + colg*8;
        float wr[8];
        #pragma unroll
        for (int c = 0; c < 8; c++) wr[c] = wp[c];
        #pragma unroll
        for (int i = 0; i < 4; i++) {
            float a = As[(4*rowg+i)*33+j];
            #pragma unroll
            for (int c = 0; c < 8; c++) acc[i][c] += a*wr[c];
        }
    }
    #pragma unroll
    for (int i = 0; i < 4; i++)
        #pragma unroll
        for (int c = 0; c < 8; c++)
            g_hid[((size_t)r0+4*rowg+i)*128 + colg*8+c] = fmaxf(acc[i][c]+sb1[colg*8+c], 0.f);
}

// ---------------- FF2 + residual + LN2, split write ; 32 rows/block, 128 thr
__global__ __launch_bounds__(128) void k_ff2(
    const float* __restrict__ w2, const float* __restrict__ b2,
    const float* __restrict__ g2, const float* __restrict__ be2,
    float* __restrict__ out)
{
    __shared__ float W2T[4096], Hs[32*129], sb[32], sg[32], sbe[32], smu[32], srs[32];
    int tid = threadIdx.x, r0 = blockIdx.x*32;
    for (int i = tid; i < 4096; i += 128) { int d = i>>7, f = i&127; W2T[f*32+d] = w2[i]; }
    if (tid < 32) { sb[tid]=b2[tid]; sg[tid]=g2[tid]; sbe[tid]=be2[tid]; }
    for (int i = tid; i < 4096; i += 128) Hs[(i>>7)*129+(i&127)] = g_hid[(size_t)r0*128+i];
    __syncthreads();

    int rowg = tid>>3, colg = tid&7;
    float4 a0 = make_float4(0,0,0,0), a1 = make_float4(0,0,0,0);
    #pragma unroll 8
    for (int f = 0; f < 128; f++) {
        float4 w4 = *(const float4*)(W2T + f*32 + colg*4);
        float h0 = Hs[(2*rowg)*129+f], h1 = Hs[(2*rowg+1)*129+f];
        a0.x += h0*w4.x; a0.y += h0*w4.y; a0.z += h0*w4.z; a0.w += h0*w4.w;
        a1.x += h1*w4.x; a1.y += h1*w4.y; a1.z += h1*w4.z; a1.w += h1*w4.w;
    }
    float4 b4 = *(const float4*)(sb + colg*4);
    float4 v0, v1;
    {
        float4 res0 = *(const float4*)(g_tok2 + ((size_t)r0+2*rowg)*32 + colg*4);
        float4 res1 = *(const float4*)(g_tok2 + ((size_t)r0+2*rowg+1)*32 + colg*4);
        v0 = make_float4(a0.x+b4.x+res0.x, a0.y+b4.y+res0.y, a0.z+b4.z+res0.z, a0.w+b4.w+res0.w);
        v1 = make_float4(a1.x+b4.x+res1.x, a1.y+b4.y+res1.y, a1.z+b4.z+res1.z, a1.w+b4.w+res1.w);
    }
    __syncthreads();              // done reading Hs; reuse as Os (stride 33)
    float* Os = Hs;
    { float* d = Os + (2*rowg)*33 + colg*4;   d[0]=v0.x; d[1]=v0.y; d[2]=v0.z; d[3]=v0.w; }
    { float* d = Os + (2*rowg+1)*33 + colg*4; d[0]=v1.x; d[1]=v1.y; d[2]=v1.z; d[3]=v1.w; }
    __syncthreads();
    if (tid < 32) {
        const float* row = Os + tid*33;
        float mu = 0.f;
        #pragma unroll
        for (int j = 0; j < 32; j++) mu += row[j];
        mu *= 0.03125f;
        float var = 0.f;
        #pragma unroll
        for (int j = 0; j < 32; j++) { float dd = row[j]-mu; var += dd*dd; }
        smu[tid] = mu; srs[tid] = rsqrtf(var*0.03125f + 1e-5f);
    }
    __syncthreads();
    for (int i = tid; i < 1024; i += 128) {
        int rr = i>>5, d = i&31;
        float o = (Os[rr*33+d]-smu[rr])*srs[rr]*sg[d] + sbe[d];
        int R = r0+rr, bt = R/20, t = R-bt*20;
        if (t < 19) out[7680 + (size_t)bt*608 + t*32 + d] = o;
        else        g_hm[(size_t)bt*32 + d] = o;
    }
}

// ---------------- BiLSTM: block = sequence, thr 0-63 fwd / 64-127 bwd
__global__ __launch_bounds__(128) void k_lstm(
    const float* __restrict__ wihf, const float* __restrict__ whhf,
    const float* __restrict__ bihf, const float* __restrict__ bhhf,
    const float* __restrict__ wihb, const float* __restrict__ whhb,
    const float* __restrict__ bihb, const float* __restrict__ bhhb)
{
    __shared__ float sx[3840], wihT[4096], whhT[2048], bias[128], sgt[128], sh[32];
    int tid = threadIdx.x, s = blockIdx.x;
    int dir = tid>>6, e = tid&63;
    for (int i = tid; i < 2048; i += 128) {
        int ee = i>>5, j = i&31;
        wihT[j*128+ee]    = wihf[i];
        wihT[j*128+64+ee] = wihb[i];
    }
    for (int i = tid; i < 1024; i += 128) {
        int ee = i>>4, j = i&15;
        whhT[j*128+ee]    = whhf[i];
        whhT[j*128+64+ee] = whhb[i];
    }
    if (tid < 64) { bias[tid] = bihf[tid]+bhhf[tid]; bias[64+tid] = bihb[tid]+bhhb[tid]; }
    for (int i = tid; i < 3840; i += 128) sx[i] = g_hm[(size_t)s*3840 + i];
    if (tid < 32) sh[tid] = 0.f;
    __syncthreads();

    float c = 0.f;
    for (int t = 0; t < 120; t++) {
        int tt = dir ? (119-t) : t;
        float g = bias[tid];
        const float* xr = sx + tt*32;
        #pragma unroll 8
        for (int j = 0; j < 32; j++) g += xr[j]*wihT[j*128+tid];
        #pragma unroll
        for (int j = 0; j < 16; j++) g += sh[dir*16+j]*whhT[j*128+tid];
        sgt[tid] = g;
        __syncthreads();
        if (e < 16) {
            float gi = sgt[dir*64+e], gf = sgt[dir*64+16+e], gg = sgt[dir*64+32+e], go = sgt[dir*64+48+e];
            float si = 1.f/(1.f+expf(-gi)), sf = 1.f/(1.f+expf(-gf)), so = 1.f/(1.f+expf(-go));
            c = sf*c + si*tanhf(gg);
            float h = so*tanhf(c);
            sh[dir*16+e] = h;
            g_hcat[((size_t)s*120+tt)*32 + dir*16 + e] = h;
        }
        __syncthreads();
    }
}

__global__ void k_lin(const float* __restrict__ lw, const float* __restrict__ lb,
                      float* __restrict__ out)
{
    int i = blockIdx.x*256 + threadIdx.x;
    if (i < 7680) {
        int bt = i>>1, o = i&1;
        const float* h = g_hcat + (size_t)bt*32;
        float acc = lb[o];
        #pragma unroll
        for (int k = 0; k < 32; k++) acc += h[k]*lw[o*32+k];
        out[i] = acc;
    }
}

extern "C" void kernel_launch(void* const* d_in, const int* in_sizes, int n_in,
                              void* d_out, int out_size)
{
    const float* x    = (const float*)d_in[0];
    const float* pos  = (const float*)d_in[1];
    const float* c1w  = (const float*)d_in[2];
    const float* c1b  = (const float*)d_in[3];
    const float* c2w  = (const float*)d_in[4];
    const float* c2b  = (const float*)d_in[5];
    const float* wq   = (const float*)d_in[6];
    const float* bq   = (const float*)d_in[7];
    const float* wk   = (const float*)d_in[8];
    const float* bk   = (const float*)d_in[9];
    const float* wv   = (const float*)d_in[10];
    const float* bv   = (const float*)d_in[11];
    const float* wo   = (const float*)d_in[12];
    const float* bo   = (const float*)d_in[13];
    const float* ln1g = (const float*)d_in[14];
    const float* ln1b = (const float*)d_in[15];
    const float* w1   = (const float*)d_in[16];
    const float* b1   = (const float*)d_in[17];
    const float* w2   = (const float*)d_in[18];
    const float* b2   = (const float*)d_in[19];
    const float* ln2g = (const float*)d_in[20];
    const float* ln2b = (const float*)d_in[21];
    const float* wihf = (const float*)d_in[22];
    const float* whhf = (const float*)d_in[23];
    const float* bihf = (const float*)d_in[24];
    const float* bhhf = (const float*)d_in[25];
    const float* wihb = (const float*)d_in[26];
    const float* whhb = (const float*)d_in[27];
    const float* bihb = (const float*)d_in[28];
    const float* bhhb = (const float*)d_in[29];
    const float* lw   = (const float*)d_in[30];
    const float* lb   = (const float*)d_in[31];
    float* out = (float*)d_out;

    k_cnn   <<<9120, 256>>>(x, c1w, c1b, c2w, c2b, pos);
    k_marker<<<480, 256>>>(pos);
    k_qkv   <<<1200, 256>>>(wq, bq, wk, bk, wv, bv);
    k_attn  <<<3840, 160>>>();
    k_proj  <<<1200, 256>>>(wo, bo, ln1g, ln1b);
    k_ff1   <<<1200, 256>>>(w1, b1);
    k_ff2   <<<2400, 128>>>(w2, b2, ln2g, ln2b, out);
    k_lstm  <<<32, 128>>>(wihf, whhf, bihf, bhhf, wihb, whhb, bihb, bhhb);
    k_lin   <<<30, 256>>>(lw, lb, out);
}

// round 3
// speedup vs baseline: 1.2542x; 1.2542x over previous
#include <cuda_runtime.h>
#include <math.h>

#define BT    3840
#define NROWS 76800

__device__ float g_tok [NROWS*32];
__device__ float g_qkv [NROWS*96];
__device__ float g_attn[NROWS*32];
__device__ float g_tok2[NROWS*32];
__device__ float g_hid [NROWS*128];
__device__ float g_hm  [BT*32];
__device__ float g_hcat[BT*32];

__constant__ unsigned c_maskb[20] = {
    0x1Fu,0x73u,0x1DDu,0x33Du,0x23Bu,0x67Au,0xC76u,0x3984u,0x779Cu,0xE738u,
    0x1CF70u,0x18CC0u,0x33180u,0x2F380u,0x6E700u,0x5EE00u,0x59C00u,0x67000u,0x7C000u,0xFFFFFu
};

__device__ __forceinline__ unsigned long long pack2(float lo, float hi){
    unsigned long long r;
    asm("mov.b64 %0, {%1, %2};" : "=l"(r) : "f"(lo), "f"(hi));
    return r;
}
__device__ __forceinline__ void unpack2(unsigned long long v, float& lo, float& hi){
    asm("mov.b64 {%0, %1}, %2;" : "=f"(lo), "=f"(hi) : "l"(v));
}
__device__ __forceinline__ void ffma2(unsigned long long& d, unsigned long long a, unsigned long long b){
    asm("fma.rn.f32x2 %0, %1, %2, %0;" : "+l"(d) : "l"(a), "l"(b));
}
__device__ __forceinline__ float fsig(float x){
    return __fdividef(1.f, 1.f + __expf(-x));
}
__device__ __forceinline__ float ftanh(float x){
    float ax = fabsf(x);
    float e  = __expf(2.f*ax);
    float t  = 1.f - __fdividef(2.f, e + 1.f);
    return (x < 0.f) ? -t : t;
}

// ---------------- CNN: warp = sample pair; conv2 via packed f32x2 FMA
// 256 thr = 8 warps = 16 samples/block. grid 4560.
__global__ __launch_bounds__(256) void k_cnn(
    const float* __restrict__ x, const float* __restrict__ c1w, const float* __restrict__ c1b,
    const float* __restrict__ c2w, const float* __restrict__ c2b, const float* __restrict__ pos)
{
    extern __shared__ __align__(16) float sm[];
    float* w2s = sm;              // 5120  [(ic*5+k)*32+oc]
    float* b2s = sm + 5120;       // 32
    float* sx  = sm + 5152;       // 3200
    float* h1p = sm + 8352;       // 8*1280   pair-interleaved [ic][t][2]

    int tid = threadIdx.x, w = tid >> 5, oc = tid & 31;
    int n0 = blockIdx.x * 16;

    for (int i = tid; i < 5120; i += 256) {
        int o = i/160, r = i - o*160, ic = r/5, k = r - ic*5;
        w2s[(ic*5+k)*32 + o] = c2w[i];
    }
    if (tid < 32) b2s[tid] = c2b[tid];
    {
        const float4* xg = (const float4*)(x + (size_t)n0*200);
        float4* sx4 = (float4*)sx;
        for (int i = tid; i < 800; i += 256) sx4[i] = xg[i];
    }
    __syncthreads();

    // ---- phase 1: conv1(s5)+relu+pool2 for both samples of the pair
    float w1r[5];
    #pragma unroll
    for (int k = 0; k < 5; k++) w1r[k] = c1w[oc*5+k];
    float b1 = c1b[oc];
    float po[2][20];
    #pragma unroll
    for (int s = 0; s < 2; s++) {
        const float* xs = sx + (2*w+s)*200;
        #pragma unroll 4
        for (int j = 0; j < 20; j++) {
            float o0 = b1, o1 = b1;
            #pragma unroll
            for (int k = 0; k < 5; k++) { o0 += xs[10*j+k]*w1r[k]; o1 += xs[10*j+5+k]*w1r[k]; }
            po[s][j] = fmaxf(fmaxf(o0,0.f), fmaxf(o1,0.f));
        }
    }
    float* hw = h1p + w*1280;
    #pragma unroll
    for (int t = 0; t < 20; t += 2) {
        float4 v = make_float4(po[0][t], po[1][t], po[0][t+1], po[1][t+1]);
        *(float4*)(hw + (oc*20 + t)*2) = v;
    }
    __syncwarp();

    // ---- phase 2: conv2(s2) accumulation over ic, packed over the sample pair
    unsigned long long acc[8];
    #pragma unroll
    for (int j = 0; j < 8; j++) acc[j] = 0ULL;
    #pragma unroll 2
    for (int ic = 0; ic < 32; ic++) {
        const ulonglong2* pv = (const ulonglong2*)(hw + ic*40);
        unsigned long long pr[20];
        #pragma unroll
        for (int q = 0; q < 10; q++) { ulonglong2 u = pv[q]; pr[2*q] = u.x; pr[2*q+1] = u.y; }
        unsigned long long wp[5];
        #pragma unroll
        for (int k = 0; k < 5; k++) { float wv_ = w2s[(ic*5+k)*32+oc]; wp[k] = pack2(wv_, wv_); }
        #pragma unroll
        for (int j = 0; j < 8; j++) {
            #pragma unroll
            for (int k = 0; k < 5; k++) ffma2(acc[j], pr[2*j+k], wp[k]);
        }
    }
    // epilogue: +bias, relu, pool2, mean4, +pos
    float aA[8], aB[8];
    #pragma unroll
    for (int j = 0; j < 8; j++) unpack2(acc[j], aA[j], aB[j]);
    float b2r = b2s[oc];
    #pragma unroll
    for (int s = 0; s < 2; s++) {
        const float* a = s ? aB : aA;
        float v = 0.f;
        #pragma unroll
        for (int u = 0; u < 4; u++)
            v += fmaxf(fmaxf(a[2*u]+b2r, 0.f), fmaxf(a[2*u+1]+b2r, 0.f));
        int n = n0 + 2*w + s, bt = n/19, c = n - bt*19;
        g_tok[((size_t)bt*20 + c)*32 + oc] = 0.25f*v + pos[c*32+oc];
    }
}

__global__ void k_marker(const float* __restrict__ pos)
{
    int i = blockIdx.x*256 + threadIdx.x;
    if (i < BT*32) { int bt = i>>5, d = i&31; g_tok[((size_t)bt*20+19)*32+d] = pos[19*32+d]; }
}

// ---------------- QKV: [64 rows,32] x [32,96]+b ; thread = 2 rows x 12 cols
__global__ __launch_bounds__(256) void k_qkv(
    const float* __restrict__ wq, const float* __restrict__ bq,
    const float* __restrict__ wk, const float* __restrict__ bk,
    const float* __restrict__ wv, const float* __restrict__ bv)
{
    __shared__ __align__(16) float WT[3072], sb[96], As[64*33];
    int tid = threadIdx.x, r0 = blockIdx.x*64;
    for (int i = tid; i < 3072; i += 256) {
        int j = i/96, n = i%96;
        WT[i] = (n<32) ? wq[n*32+j] : (n<64) ? wk[(n-32)*32+j] : wv[(n-64)*32+j];
    }
    for (int i = tid; i < 96; i += 256) sb[i] = (i<32)?bq[i]:(i<64)?bk[i-32]:bv[i-64];
    for (int i = tid; i < 2048; i += 256) As[(i>>5)*33 + (i&31)] = g_tok[(size_t)r0*32 + i];
    __syncthreads();

    int rowg = tid>>3, colg = tid&7;
    float acc0[12], acc1[12];
    #pragma unroll
    for (int c = 0; c < 12; c++) { acc0[c]=0.f; acc1[c]=0.f; }
    #pragma unroll 8
    for (int j = 0; j < 32; j++) {
        float a0 = As[(2*rowg)*33+j], a1 = As[(2*rowg+1)*33+j];
        const float4* wp4 = (const float4*)(WT + j*96 + colg*12);
        float4 wv4[3]; wv4[0]=wp4[0]; wv4[1]=wp4[1]; wv4[2]=wp4[2];
        const float* wr = (const float*)wv4;
        #pragma unroll
        for (int c = 0; c < 12; c++) { float ww = wr[c]; acc0[c] += a0*ww; acc1[c] += a1*ww; }
    }
    #pragma unroll
    for (int c = 0; c < 12; c++) {
        float b = sb[colg*12+c];
        g_qkv[((size_t)r0+2*rowg)*96 + colg*12+c]   = acc0[c]+b;
        g_qkv[((size_t)r0+2*rowg+1)*96 + colg*12+c] = acc1[c]+b;
    }
}

// ---------------- attention per sample; thread = (t, head); all-register softmax
__global__ __launch_bounds__(160) void k_attn()
{
    __shared__ __align__(16) float qs[720], ks[720], vs[720];
    int tid = threadIdx.x, bt = blockIdx.x;
    const float* base = g_qkv + (size_t)bt*1920;
    for (int i = tid; i < 1920; i += 160) {
        int t = i/96, c = i%96; float v = base[i];
        if (c<32) qs[t*36+c]=v; else if (c<64) ks[t*36+c-32]=v; else vs[t*36+c-64]=v;
    }
    __syncthreads();
    int t = tid>>3, h = tid&7;
    float4 q4 = *(const float4*)(qs + t*36 + h*4);
    unsigned mb = c_maskb[t];
    float sc[20], mx = -1e30f;
    #pragma unroll
    for (int kt = 0; kt < 20; kt++) {
        float4 k4 = *(const float4*)(ks + kt*36 + h*4);
        float s = 0.5f*(q4.x*k4.x+q4.y*k4.y+q4.z*k4.z+q4.w*k4.w);
        if (!((mb>>kt)&1u)) s = -1e9f;
        sc[kt] = s; mx = fmaxf(mx, s);
    }
    float sum = 0.f;
    #pragma unroll
    for (int kt = 0; kt < 20; kt++) { sc[kt] = __expf(sc[kt]-mx); sum += sc[kt]; }
    float inv = __fdividef(1.f, sum);
    float4 o = make_float4(0.f,0.f,0.f,0.f);
    #pragma unroll
    for (int kt = 0; kt < 20; kt++) {
        float a = sc[kt];
        float4 v4 = *(const float4*)(vs + kt*36 + h*4);
        o.x += a*v4.x; o.y += a*v4.y; o.z += a*v4.z; o.w += a*v4.w;
    }
    o.x *= inv; o.y *= inv; o.z *= inv; o.w *= inv;
    *(float4*)(g_attn + ((size_t)bt*20+t)*32 + h*4) = o;
}

// ---------------- proj + residual + LN1 -> g_tok2 ; 64 rows/block
__global__ __launch_bounds__(256) void k_proj(
    const float* __restrict__ wo, const float* __restrict__ bo,
    const float* __restrict__ g1, const float* __restrict__ be1)
{
    __shared__ __align__(16) float WT[1024], As[64*33], Os[64*33], sb[32], sg[32], sbe[32], smu[64], srs[64];
    int tid = threadIdx.x, r0 = blockIdx.x*64;
    for (int i = tid; i < 1024; i += 256) { int d = i>>5, j = i&31; WT[j*32+d] = wo[i]; }
    if (tid < 32) { sb[tid]=bo[tid]; sg[tid]=g1[tid]; sbe[tid]=be1[tid]; }
    for (int i = tid; i < 2048; i += 256) As[(i>>5)*33+(i&31)] = g_attn[(size_t)r0*32+i];
    __syncthreads();

    int rowg = tid>>3, colg = tid&7;
    float4 a0 = make_float4(0,0,0,0), a1 = make_float4(0,0,0,0);
    #pragma unroll 8
    for (int j = 0; j < 32; j++) {
        float4 w4 = *(const float4*)(WT + j*32 + colg*4);
        float x0 = As[(2*rowg)*33+j], x1 = As[(2*rowg+1)*33+j];
        a0.x += x0*w4.x; a0.y += x0*w4.y; a0.z += x0*w4.z; a0.w += x0*w4.w;
        a1.x += x1*w4.x; a1.y += x1*w4.y; a1.z += x1*w4.z; a1.w += x1*w4.w;
    }
    float4 b4 = *(const float4*)(sb + colg*4);
    #pragma unroll
    for (int i = 0; i < 2; i++) {
        int rr = 2*rowg+i;
        float4 res = *(const float4*)(g_tok + ((size_t)r0+rr)*32 + colg*4);
        float4 ac = i ? a1 : a0;
        float* d = Os + rr*33 + colg*4;
        d[0]=ac.x+b4.x+res.x; d[1]=ac.y+b4.y+res.y; d[2]=ac.z+b4.z+res.z; d[3]=ac.w+b4.w+res.w;
    }
    __syncthreads();
    if (tid < 64) {
        const float* row = Os + tid*33;
        float mu = 0.f;
        #pragma unroll
        for (int j = 0; j < 32; j++) mu += row[j];
        mu *= 0.03125f;
        float var = 0.f;
        #pragma unroll
        for (int j = 0; j < 32; j++) { float dd = row[j]-mu; var += dd*dd; }
        smu[tid] = mu; srs[tid] = rsqrtf(var*0.03125f + 1e-5f);
    }
    __syncthreads();
    for (int i = tid; i < 2048; i += 256) {
        int rr = i>>5, d = i&31;
        g_tok2[(size_t)r0*32+i] = (Os[rr*33+d]-smu[rr])*srs[rr]*sg[d] + sbe[d];
    }
}

// ---------------- FF1: relu([64,32]x[32,128]+b) -> g_hid ; thread = 4 rows x 8 cols
__global__ __launch_bounds__(256) void k_ff1(
    const float* __restrict__ w1, const float* __restrict__ b1)
{
    __shared__ __align__(16) float W1T[4096], sb1[128], As[64*33];
    int tid = threadIdx.x, r0 = blockIdx.x*64;
    for (int i = tid; i < 4096; i += 256) { int f = i>>5, j = i&31; W1T[j*128+f] = w1[i]; }
    if (tid < 128) sb1[tid] = b1[tid];
    for (int i = tid; i < 2048; i += 256) As[(i>>5)*33+(i&31)] = g_tok2[(size_t)r0*32+i];
    __syncthreads();

    int rowg = tid>>4, colg = tid&15;
    float acc[4][8];
    #pragma unroll
    for (int i = 0; i < 4; i++)
        #pragma unroll
        for (int c = 0; c < 8; c++) acc[i][c] = 0.f;
    #pragma unroll 4
    for (int j = 0; j < 32; j++) {
        const float4* wp4 = (const float4*)(W1T + j*128 + colg*8);
        float4 wa = wp4[0], wb = wp4[1];
        float wr[8] = {wa.x,wa.y,wa.z,wa.w, wb.x,wb.y,wb.z,wb.w};
        #pragma unroll
        for (int i = 0; i < 4; i++) {
            float a = As[(4*rowg+i)*33+j];
            #pragma unroll
            for (int c = 0; c < 8; c++) acc[i][c] += a*wr[c];
        }
    }
    #pragma unroll
    for (int i = 0; i < 4; i++)
        #pragma unroll
        for (int c = 0; c < 8; c++)
            g_hid[((size_t)r0+4*rowg+i)*128 + colg*8+c] = fmaxf(acc[i][c]+sb1[colg*8+c], 0.f);
}

// ---------------- FF2 + residual + LN2, split write ; 32 rows/block, 128 thr
__global__ __launch_bounds__(128) void k_ff2(
    const float* __restrict__ w2, const float* __restrict__ b2,
    const float* __restrict__ g2, const float* __restrict__ be2,
    float* __restrict__ out)
{
    __shared__ __align__(16) float W2T[4096], Hs[32*129], sb[32], sg[32], sbe[32], smu[32], srs[32];
    int tid = threadIdx.x, r0 = blockIdx.x*32;
    for (int i = tid; i < 4096; i += 128) { int d = i>>7, f = i&127; W2T[f*32+d] = w2[i]; }
    if (tid < 32) { sb[tid]=b2[tid]; sg[tid]=g2[tid]; sbe[tid]=be2[tid]; }
    for (int i = tid; i < 4096; i += 128) Hs[(i>>7)*129+(i&127)] = g_hid[(size_t)r0*128+i];
    __syncthreads();

    int rowg = tid>>3, colg = tid&7;
    float4 a0 = make_float4(0,0,0,0), a1 = make_float4(0,0,0,0);
    #pragma unroll 8
    for (int f = 0; f < 128; f++) {
        float4 w4 = *(const float4*)(W2T + f*32 + colg*4);
        float h0 = Hs[(2*rowg)*129+f], h1 = Hs[(2*rowg+1)*129+f];
        a0.x += h0*w4.x; a0.y += h0*w4.y; a0.z += h0*w4.z; a0.w += h0*w4.w;
        a1.x += h1*w4.x; a1.y += h1*w4.y; a1.z += h1*w4.z; a1.w += h1*w4.w;
    }
    float4 b4 = *(const float4*)(sb + colg*4);
    float4 v0, v1;
    {
        float4 res0 = *(const float4*)(g_tok2 + ((size_t)r0+2*rowg)*32 + colg*4);
        float4 res1 = *(const float4*)(g_tok2 + ((size_t)r0+2*rowg+1)*32 + colg*4);
        v0 = make_float4(a0.x+b4.x+res0.x, a0.y+b4.y+res0.y, a0.z+b4.z+res0.z, a0.w+b4.w+res0.w);
        v1 = make_float4(a1.x+b4.x+res1.x, a1.y+b4.y+res1.y, a1.z+b4.z+res1.z, a1.w+b4.w+res1.w);
    }
    __syncthreads();
    float* Os = Hs;
    { float* d = Os + (2*rowg)*33 + colg*4;   d[0]=v0.x; d[1]=v0.y; d[2]=v0.z; d[3]=v0.w; }
    { float* d = Os + (2*rowg+1)*33 + colg*4; d[0]=v1.x; d[1]=v1.y; d[2]=v1.z; d[3]=v1.w; }
    __syncthreads();
    if (tid < 32) {
        const float* row = Os + tid*33;
        float mu = 0.f;
        #pragma unroll
        for (int j = 0; j < 32; j++) mu += row[j];
        mu *= 0.03125f;
        float var = 0.f;
        #pragma unroll
        for (int j = 0; j < 32; j++) { float dd = row[j]-mu; var += dd*dd; }
        smu[tid] = mu; srs[tid] = rsqrtf(var*0.03125f + 1e-5f);
    }
    __syncthreads();
    for (int i = tid; i < 1024; i += 128) {
        int rr = i>>5, d = i&31;
        float o = (Os[rr*33+d]-smu[rr])*srs[rr]*sg[d] + sbe[d];
        int R = r0+rr, bt = R/20, t = R-bt*20;
        if (t < 19) out[7680 + (size_t)bt*608 + t*32 + d] = o;
        else        g_hm[(size_t)bt*32 + d] = o;
    }
}

// ---------------- BiLSTM: block = sequence, thr 0-63 fwd / 64-127 bwd
__global__ __launch_bounds__(128) void k_lstm(
    const float* __restrict__ wihf, const float* __restrict__ whhf,
    const float* __restrict__ bihf, const float* __restrict__ bhhf,
    const float* __restrict__ wihb, const float* __restrict__ whhb,
    const float* __restrict__ bihb, const float* __restrict__ bhhb)
{
    __shared__ __align__(16) float sx[3840], wihT[4096], whhT[2048], bias[128], sgt[128], sh[32];
    int tid = threadIdx.x, s = blockIdx.x;
    int dir = tid>>6, e = tid&63;
    for (int i = tid; i < 2048; i += 128) {
        int ee = i>>5, j = i&31;
        wihT[j*128+ee]    = wihf[i];
        wihT[j*128+64+ee] = wihb[i];
    }
    for (int i = tid; i < 1024; i += 128) {
        int ee = i>>4, j = i&15;
        whhT[j*128+ee]    = whhf[i];
        whhT[j*128+64+ee] = whhb[i];
    }
    if (tid < 64) { bias[tid] = bihf[tid]+bhhf[tid]; bias[64+tid] = bihb[tid]+bhhb[tid]; }
    for (int i = tid; i < 3840; i += 128) sx[i] = g_hm[(size_t)s*3840 + i];
    if (tid < 32) sh[tid] = 0.f;
    __syncthreads();

    float c = 0.f;
    for (int t = 0; t < 120; t++) {
        int tt = dir ? (119-t) : t;
        const float* xr = sx + tt*32;
        float a0=0.f, a1=0.f, a2=0.f, a3=0.f;
        #pragma unroll
        for (int j = 0; j < 32; j += 4) {
            a0 = fmaf(xr[j+0], wihT[(j+0)*128+tid], a0);
            a1 = fmaf(xr[j+1], wihT[(j+1)*128+tid], a1);
            a2 = fmaf(xr[j+2], wihT[(j+2)*128+tid], a2);
            a3 = fmaf(xr[j+3], wihT[(j+3)*128+tid], a3);
        }
        const float* hp = sh + dir*16;
        #pragma unroll
        for (int j = 0; j < 16; j += 4) {
            a0 = fmaf(hp[j+0], whhT[(j+0)*128+tid], a0);
            a1 = fmaf(hp[j+1], whhT[(j+1)*128+tid], a1);
            a2 = fmaf(hp[j+2], whhT[(j+2)*128+tid], a2);
            a3 = fmaf(hp[j+3], whhT[(j+3)*128+tid], a3);
        }
        sgt[tid] = bias[tid] + (a0+a1) + (a2+a3);
        __syncthreads();
        if (e < 16) {
            float gi = sgt[dir*64+e], gf = sgt[dir*64+16+e], gg = sgt[dir*64+32+e], go = sgt[dir*64+48+e];
            c = fsig(gf)*c + fsig(gi)*ftanh(gg);
            float h = fsig(go)*ftanh(c);
            sh[dir*16+e] = h;
            g_hcat[((size_t)s*120+tt)*32 + dir*16 + e] = h;
        }
        __syncthreads();
    }
}

__global__ void k_lin(const float* __restrict__ lw, const float* __restrict__ lb,
                      float* __restrict__ out)
{
    int i = blockIdx.x*256 + threadIdx.x;
    if (i < 7680) {
        int bt = i>>1, o = i&1;
        const float* h = g_hcat + (size_t)bt*32;
        float acc = lb[o];
        #pragma unroll
        for (int k = 0; k < 32; k++) acc += h[k]*lw[o*32+k];
        out[i] = acc;
    }
}

extern "C" void kernel_launch(void* const* d_in, const int* in_sizes, int n_in,
                              void* d_out, int out_size)
{
    const float* x    = (const float*)d_in[0];
    const float* pos  = (const float*)d_in[1];
    const float* c1w  = (const float*)d_in[2];
    const float* c1b  = (const float*)d_in[3];
    const float* c2w  = (const float*)d_in[4];
    const float* c2b  = (const float*)d_in[5];
    const float* wq   = (const float*)d_in[6];
    const float* bq   = (const float*)d_in[7];
    const float* wk   = (const float*)d_in[8];
    const float* bk   = (const float*)d_in[9];
    const float* wv   = (const float*)d_in[10];
    const float* bv   = (const float*)d_in[11];
    const float* wo   = (const float*)d_in[12];
    const float* bo   = (const float*)d_in[13];
    const float* ln1g = (const float*)d_in[14];
    const float* ln1b = (const float*)d_in[15];
    const float* w1   = (const float*)d_in[16];
    const float* b1   = (const float*)d_in[17];
    const float* w2   = (const float*)d_in[18];
    const float* b2   = (const float*)d_in[19];
    const float* ln2g = (const float*)d_in[20];
    const float* ln2b = (const float*)d_in[21];
    const float* wihf = (const float*)d_in[22];
    const float* whhf = (const float*)d_in[23];
    const float* bihf = (const float*)d_in[24];
    const float* bhhf = (const float*)d_in[25];
    const float* wihb = (const float*)d_in[26];
    const float* whhb = (const float*)d_in[27];
    const float* bihb = (const float*)d_in[28];
    const float* bhhb = (const float*)d_in[29];
    const float* lw   = (const float*)d_in[30];
    const float* lb   = (const float*)d_in[31];
    float* out = (float*)d_out;

    cudaFuncSetAttribute(k_cnn, cudaFuncAttributeMaxDynamicSharedMemorySize, 80*1024);
    k_cnn   <<<4560, 256, 74368>>>(x, c1w, c1b, c2w, c2b, pos);
    k_marker<<<480, 256>>>(pos);
    k_qkv   <<<1200, 256>>>(wq, bq, wk, bk, wv, bv);
    k_attn  <<<3840, 160>>>();
    k_proj  <<<1200, 256>>>(wo, bo, ln1g, ln1b);
    k_ff1   <<<1200, 256>>>(w1, b1);
    k_ff2   <<<2400, 128>>>(w2, b2, ln2g, ln2b, out);
    k_lstm  <<<32, 128>>>(wihf, whhf, bihf, bhhf, wihb, whhb, bihb, bhhb);
    k_lin   <<<30, 256>>>(lw, lb, out);
}

// round 4
// speedup vs baseline: 1.5203x; 1.2121x over previous
#include <cuda_runtime.h>
#include <math.h>

#define BT    3840
#define NROWS 76800

__device__ float g_tok [BT*19*32];
__device__ float g_tok2[NROWS*32];
__device__ float g_hm  [BT*32];
__device__ float g_hcat[BT*32];

__constant__ unsigned c_maskb[20] = {
    0x1Fu,0x73u,0x1DDu,0x33Du,0x23Bu,0x67Au,0xC76u,0x3984u,0x779Cu,0xE738u,
    0x1CF70u,0x18CC0u,0x33180u,0x2F380u,0x6E700u,0x5EE00u,0x59C00u,0x67000u,0x7C000u,0xFFFFFu
};

__device__ __forceinline__ unsigned long long pack2(float lo, float hi){
    unsigned long long r;
    asm("mov.b64 %0, {%1, %2};" : "=l"(r) : "f"(lo), "f"(hi));
    return r;
}
__device__ __forceinline__ void unpack2(unsigned long long v, float& lo, float& hi){
    asm("mov.b64 {%0, %1}, %2;" : "=f"(lo), "=f"(hi) : "l"(v));
}
__device__ __forceinline__ void ffma2(unsigned long long& d, unsigned long long a, unsigned long long b){
    asm("fma.rn.f32x2 %0, %1, %2, %0;" : "+l"(d) : "l"(a), "l"(b));
}
__device__ __forceinline__ float fsig(float x){ return __fdividef(1.f, 1.f + __expf(-x)); }
__device__ __forceinline__ float ftanh(float x){
    float ax = fabsf(x);
    float e  = __expf(2.f*ax);
    float t  = 1.f - __fdividef(2.f, e + 1.f);
    return (x < 0.f) ? -t : t;
}

// ---------------- CNN: warp = sample pair; conv2 via packed f32x2 FMA
__global__ __launch_bounds__(256) void k_cnn(
    const float* __restrict__ x, const float* __restrict__ c1w, const float* __restrict__ c1b,
    const float* __restrict__ c2w, const float* __restrict__ c2b, const float* __restrict__ pos)
{
    extern __shared__ __align__(16) float sm[];
    float* w2s = sm;              // 5120
    float* b2s = sm + 5120;       // 32
    float* sx  = sm + 5152;       // 3200
    float* h1p = sm + 8352;       // 8*1280

    int tid = threadIdx.x, w = tid >> 5, oc = tid & 31;
    int n0 = blockIdx.x * 16;

    for (int i = tid; i < 5120; i += 256) {
        int o = i/160, r = i - o*160, ic = r/5, k = r - ic*5;
        w2s[(ic*5+k)*32 + o] = c2w[i];
    }
    if (tid < 32) b2s[tid] = c2b[tid];
    {
        const float4* xg = (const float4*)(x + (size_t)n0*200);
        float4* sx4 = (float4*)sx;
        for (int i = tid; i < 800; i += 256) sx4[i] = xg[i];
    }
    __syncthreads();

    float w1r[5];
    #pragma unroll
    for (int k = 0; k < 5; k++) w1r[k] = c1w[oc*5+k];
    float b1 = c1b[oc];
    float po[2][20];
    #pragma unroll
    for (int s = 0; s < 2; s++) {
        const float* xs = sx + (2*w+s)*200;
        #pragma unroll 4
        for (int j = 0; j < 20; j++) {
            float o0 = b1, o1 = b1;
            #pragma unroll
            for (int k = 0; k < 5; k++) { o0 += xs[10*j+k]*w1r[k]; o1 += xs[10*j+5+k]*w1r[k]; }
            po[s][j] = fmaxf(fmaxf(o0,0.f), fmaxf(o1,0.f));
        }
    }
    float* hw = h1p + w*1280;
    #pragma unroll
    for (int t = 0; t < 20; t += 2) {
        float4 v = make_float4(po[0][t], po[1][t], po[0][t+1], po[1][t+1]);
        *(float4*)(hw + (oc*20 + t)*2) = v;
    }
    __syncwarp();

    unsigned long long acc[8];
    #pragma unroll
    for (int j = 0; j < 8; j++) acc[j] = 0ULL;
    #pragma unroll 2
    for (int ic = 0; ic < 32; ic++) {
        const ulonglong2* pv = (const ulonglong2*)(hw + ic*40);
        unsigned long long pr[20];
        #pragma unroll
        for (int q = 0; q < 10; q++) { ulonglong2 u = pv[q]; pr[2*q] = u.x; pr[2*q+1] = u.y; }
        unsigned long long wp[5];
        #pragma unroll
        for (int k = 0; k < 5; k++) { float wv_ = w2s[(ic*5+k)*32+oc]; wp[k] = pack2(wv_, wv_); }
        #pragma unroll
        for (int j = 0; j < 8; j++) {
            #pragma unroll
            for (int k = 0; k < 5; k++) ffma2(acc[j], pr[2*j+k], wp[k]);
        }
    }
    float aA[8], aB[8];
    #pragma unroll
    for (int j = 0; j < 8; j++) unpack2(acc[j], aA[j], aB[j]);
    float b2r = b2s[oc];
    #pragma unroll
    for (int s = 0; s < 2; s++) {
        const float* a = s ? aB : aA;
        float v = 0.f;
        #pragma unroll
        for (int u = 0; u < 4; u++)
            v += fmaxf(fmaxf(a[2*u]+b2r, 0.f), fmaxf(a[2*u+1]+b2r, 0.f));
        int n = n0 + 2*w + s, c = n % 19;
        g_tok[(size_t)n*32 + oc] = 0.25f*v + pos[c*32+oc];
    }
}

// ---------------- fused QKV + attention + proj + LN1 ; 4 samples/block, 320 thr
__global__ __launch_bounds__(320) void k_xform(
    const float* __restrict__ wq, const float* __restrict__ bq,
    const float* __restrict__ wk, const float* __restrict__ bk,
    const float* __restrict__ wv, const float* __restrict__ bv,
    const float* __restrict__ wo, const float* __restrict__ bo,
    const float* __restrict__ g1, const float* __restrict__ be1,
    const float* __restrict__ pos)
{
    extern __shared__ __align__(16) float sm[];
    float* WT   = sm;            // 3072  qkv weights [j][96]
    float* sbq  = sm + 3072;     // 96
    float* WOT  = sm + 3168;     // 1024  [j][32]
    float* sbo  = sm + 4192;     // 32
    float* sg   = sm + 4224;     // 32
    float* sbe  = sm + 4256;     // 32
    float* As   = sm + 4288;     // 80*33
    float* QKV  = sm + 6928;     // 4*2160  per sample: q[20*36] k v
    float* Os   = sm + 15568;    // 80*36 attn output (stride 36 for aligned float4)
    float* smu  = sm + 18448;    // 80
    float* srs  = sm + 18528;    // 80
    // total 18608 floats = 74432 B

    int tid = threadIdx.x;
    int s0 = blockIdx.x * 4;

    for (int i = tid; i < 3072; i += 320) {
        int j = i/96, n = i%96;
        WT[i] = (n<32) ? wq[n*32+j] : (n<64) ? wk[(n-32)*32+j] : wv[(n-64)*32+j];
    }
    for (int i = tid; i < 96; i += 320) sbq[i] = (i<32)?bq[i]:(i<64)?bk[i-32]:bv[i-64];
    for (int i = tid; i < 1024; i += 320) { int d = i>>5, j = i&31; WOT[j*32+d] = wo[i]; }
    if (tid < 32) { sbo[tid]=bo[tid]; sg[tid]=g1[tid]; sbe[tid]=be1[tid]; }
    // load 80 token rows (t<19 from g_tok, t==19 from pos)
    for (int i = tid; i < 640; i += 320) {
        int rr = i>>3, d4 = (i&7)*4;
        int sl = rr/20, t = rr - sl*20;
        const float4 v = (t < 19)
            ? *(const float4*)(g_tok + ((size_t)(s0+sl)*19 + t)*32 + d4)
            : *(const float4*)(pos + 19*32 + d4);
        float* d = As + rr*33 + d4;
        d[0]=v.x; d[1]=v.y; d[2]=v.z; d[3]=v.w;
    }
    __syncthreads();

    // ---- QKV gemm: thread = 2 rows x 12 cols
    {
        int rowg = tid>>3, colg = tid&7;   // rowg 0..39
        float acc0[12], acc1[12];
        #pragma unroll
        for (int c = 0; c < 12; c++) { acc0[c]=0.f; acc1[c]=0.f; }
        #pragma unroll 8
        for (int j = 0; j < 32; j++) {
            float a0 = As[(2*rowg)*33+j], a1 = As[(2*rowg+1)*33+j];
            const float4* wp4 = (const float4*)(WT + j*96 + colg*12);
            float4 wv4[3]; wv4[0]=wp4[0]; wv4[1]=wp4[1]; wv4[2]=wp4[2];
            const float* wr = (const float*)wv4;
            #pragma unroll
            for (int c = 0; c < 12; c++) { float ww = wr[c]; acc0[c] += a0*ww; acc1[c] += a1*ww; }
        }
        #pragma unroll
        for (int c = 0; c < 12; c++) {
            int n = colg*12 + c;
            int which = n>>5, d = n&31;
            float b = sbq[n];
            int rr0 = 2*rowg, rr1 = rr0+1;
            int sl0 = rr0/20, t0 = rr0 - sl0*20;
            int sl1 = rr1/20, t1 = rr1 - sl1*20;
            QKV[sl0*2160 + which*720 + t0*36 + d] = acc0[c] + b;
            QKV[sl1*2160 + which*720 + t1*36 + d] = acc1[c] + b;
        }
    }
    __syncthreads();

    // ---- attention: 2 passes x 320 threads = 640 (sample, t, h) items
    #pragma unroll
    for (int pass = 0; pass < 2; pass++) {
        int hi = (tid >= 160);
        int sl = pass*2 + hi;
        int slot = tid - hi*160;
        int t = slot>>3, h = slot&7;
        const float* qs = QKV + sl*2160;
        const float* ks = qs + 720;
        const float* vs = qs + 1440;
        float4 q4 = *(const float4*)(qs + t*36 + h*4);
        unsigned mb = c_maskb[t];
        float sc[20], mx = -1e30f;
        #pragma unroll
        for (int kt = 0; kt < 20; kt++) {
            float4 k4 = *(const float4*)(ks + kt*36 + h*4);
            float s = 0.5f*(q4.x*k4.x+q4.y*k4.y+q4.z*k4.z+q4.w*k4.w);
            if (!((mb>>kt)&1u)) s = -1e9f;
            sc[kt] = s; mx = fmaxf(mx, s);
        }
        float sum = 0.f;
        #pragma unroll
        for (int kt = 0; kt < 20; kt++) { sc[kt] = __expf(sc[kt]-mx); sum += sc[kt]; }
        float inv = __fdividef(1.f, sum);
        float4 o = make_float4(0.f,0.f,0.f,0.f);
        #pragma unroll
        for (int kt = 0; kt < 20; kt++) {
            float a = sc[kt];
            float4 v4 = *(const float4*)(vs + kt*36 + h*4);
            o.x += a*v4.x; o.y += a*v4.y; o.z += a*v4.z; o.w += a*v4.w;
        }
        o.x *= inv; o.y *= inv; o.z *= inv; o.w *= inv;
        *(float4*)(Os + (sl*20 + t)*36 + h*4) = o;
    }
    __syncthreads();

    // ---- proj: thread = 2 rows x 4 cols ; +bias +residual -> Ps (reuse QKV, stride 33)
    float* Ps = QKV;
    {
        int rowg = tid>>3, colg = tid&7;
        float4 a0 = make_float4(0,0,0,0), a1 = make_float4(0,0,0,0);
        #pragma unroll 8
        for (int j = 0; j < 32; j++) {
            float4 w4 = *(const float4*)(WOT + j*32 + colg*4);
            float x0 = Os[(2*rowg)*36+j], x1 = Os[(2*rowg+1)*36+j];
            a0.x += x0*w4.x; a0.y += x0*w4.y; a0.z += x0*w4.z; a0.w += x0*w4.w;
            a1.x += x1*w4.x; a1.y += x1*w4.y; a1.z += x1*w4.z; a1.w += x1*w4.w;
        }
        #pragma unroll
        for (int i = 0; i < 2; i++) {
            int rr = 2*rowg + i;
            const float* res = As + rr*33 + colg*4;
            float4 ac = i ? a1 : a0;
            float* d = Ps + rr*33 + colg*4;
            d[0]=ac.x+sbo[colg*4+0]+res[0];
            d[1]=ac.y+sbo[colg*4+1]+res[1];
            d[2]=ac.z+sbo[colg*4+2]+res[2];
            d[3]=ac.w+sbo[colg*4+3]+res[3];
        }
    }
    __syncthreads();
    if (tid < 80) {
        const float* row = Ps + tid*33;
        float mu = 0.f;
        #pragma unroll
        for (int j = 0; j < 32; j++) mu += row[j];
        mu *= 0.03125f;
        float var = 0.f;
        #pragma unroll
        for (int j = 0; j < 32; j++) { float dd = row[j]-mu; var += dd*dd; }
        smu[tid] = mu; srs[tid] = rsqrtf(var*0.03125f + 1e-5f);
    }
    __syncthreads();
    size_t base = (size_t)blockIdx.x * 80 * 32;
    for (int i = tid; i < 2560; i += 320) {
        int rr = i>>5, d = i&31;
        g_tok2[base + i] = (Ps[rr*33+d]-smu[rr])*srs[rr]*sg[d] + sbe[d];
    }
}

// ---------------- fused FF1+ReLU+FF2+residual+LN2 + split write ; 4 samples/block
__global__ __launch_bounds__(320) void k_ffn(
    const float* __restrict__ w1, const float* __restrict__ b1,
    const float* __restrict__ w2, const float* __restrict__ b2,
    const float* __restrict__ g2, const float* __restrict__ be2,
    float* __restrict__ out)
{
    extern __shared__ __align__(16) float sm[];
    float* W1T = sm;             // 4096 [j][128]
    float* sb1 = sm + 4096;      // 128
    float* W2T = sm + 4224;      // 4096 [f][32]
    float* sb2 = sm + 8320;      // 32
    float* sg  = sm + 8352;      // 32
    float* sbe = sm + 8384;      // 32
    float* As  = sm + 8416;      // 80*33
    float* Hs  = sm + 11056;     // 80*132
    float* smu = sm + 21616;     // 80
    float* srs = sm + 21696;     // 80
    // total 21776 floats = 87104 B

    int tid = threadIdx.x;
    int s0 = blockIdx.x * 4;
    size_t base = (size_t)blockIdx.x * 80 * 32;

    for (int i = tid; i < 4096; i += 320) {
        { int f = i>>5, j = i&31;  W1T[j*128+f] = w1[i]; }
        { int d = i>>7, f = i&127; W2T[f*32+d]  = w2[i]; }
    }
    if (tid < 128) sb1[tid] = b1[tid];
    if (tid < 32) { sb2[tid]=b2[tid]; sg[tid]=g2[tid]; sbe[tid]=be2[tid]; }
    for (int i = tid; i < 2560; i += 320) As[(i>>5)*33+(i&31)] = g_tok2[base + i];
    __syncthreads();

    // ---- FF1: thread = 4 rows x 8 cols
    {
        int rowg = tid>>4, colg = tid&15;  // rowg 0..19
        float acc[4][8];
        #pragma unroll
        for (int i = 0; i < 4; i++)
            #pragma unroll
            for (int c = 0; c < 8; c++) acc[i][c] = 0.f;
        #pragma unroll 4
        for (int j = 0; j < 32; j++) {
            const float4* wp4 = (const float4*)(W1T + j*128 + colg*8);
            float4 wa = wp4[0], wb = wp4[1];
            float wr[8] = {wa.x,wa.y,wa.z,wa.w, wb.x,wb.y,wb.z,wb.w};
            #pragma unroll
            for (int i = 0; i < 4; i++) {
                float a = As[(4*rowg+i)*33+j];
                #pragma unroll
                for (int c = 0; c < 8; c++) acc[i][c] += a*wr[c];
            }
        }
        #pragma unroll
        for (int i = 0; i < 4; i++)
            #pragma unroll
            for (int c = 0; c < 8; c++)
                Hs[(4*rowg+i)*132 + colg*8+c] = fmaxf(acc[i][c]+sb1[colg*8+c], 0.f);
    }
    __syncthreads();

    // ---- FF2: thread = 2 rows x 4 cols, + bias + residual
    int rowg = tid>>3, colg = tid&7;
    float4 v0, v1;
    {
        float4 a0 = make_float4(0,0,0,0), a1 = make_float4(0,0,0,0);
        #pragma unroll 8
        for (int f = 0; f < 128; f++) {
            float4 w4 = *(const float4*)(W2T + f*32 + colg*4);
            float h0 = Hs[(2*rowg)*132+f], h1 = Hs[(2*rowg+1)*132+f];
            a0.x += h0*w4.x; a0.y += h0*w4.y; a0.z += h0*w4.z; a0.w += h0*w4.w;
            a1.x += h1*w4.x; a1.y += h1*w4.y; a1.z += h1*w4.z; a1.w += h1*w4.w;
        }
        const float* r0 = As + (2*rowg)*33 + colg*4;
        const float* r1 = As + (2*rowg+1)*33 + colg*4;
        v0 = make_float4(a0.x+sb2[colg*4+0]+r0[0], a0.y+sb2[colg*4+1]+r0[1],
                         a0.z+sb2[colg*4+2]+r0[2], a0.w+sb2[colg*4+3]+r0[3]);
        v1 = make_float4(a1.x+sb2[colg*4+0]+r1[0], a1.y+sb2[colg*4+1]+r1[1],
                         a1.z+sb2[colg*4+2]+r1[2], a1.w+sb2[colg*4+3]+r1[3]);
    }
    __syncthreads();
    float* Ps = Hs;   // reuse, stride 33
    { float* d = Ps + (2*rowg)*33 + colg*4;   d[0]=v0.x; d[1]=v0.y; d[2]=v0.z; d[3]=v0.w; }
    { float* d = Ps + (2*rowg+1)*33 + colg*4; d[0]=v1.x; d[1]=v1.y; d[2]=v1.z; d[3]=v1.w; }
    __syncthreads();
    if (tid < 80) {
        const float* row = Ps + tid*33;
        float mu = 0.f;
        #pragma unroll
        for (int j = 0; j < 32; j++) mu += row[j];
        mu *= 0.03125f;
        float var = 0.f;
        #pragma unroll
        for (int j = 0; j < 32; j++) { float dd = row[j]-mu; var += dd*dd; }
        smu[tid] = mu; srs[tid] = rsqrtf(var*0.03125f + 1e-5f);
    }
    __syncthreads();
    for (int i = tid; i < 2560; i += 320) {
        int rr = i>>5, d = i&31;
        float o = (Ps[rr*33+d]-smu[rr])*srs[rr]*sg[d] + sbe[d];
        int sl = rr/20, t = rr - sl*20;
        int bt = s0 + sl;
        if (t < 19) out[7680 + (size_t)bt*608 + t*32 + d] = o;
        else        g_hm[(size_t)bt*32 + d] = o;
    }
}

// ---------------- BiLSTM: block = sequence, thr 0-63 fwd / 64-127 bwd
__global__ __launch_bounds__(128) void k_lstm(
    const float* __restrict__ wihf, const float* __restrict__ whhf,
    const float* __restrict__ bihf, const float* __restrict__ bhhf,
    const float* __restrict__ wihb, const float* __restrict__ whhb,
    const float* __restrict__ bihb, const float* __restrict__ bhhb)
{
    __shared__ __align__(16) float sx[3840], wihT[4096], whhT[2048], bias[128], sgt[128], sh[32];
    int tid = threadIdx.x, s = blockIdx.x;
    int dir = tid>>6, e = tid&63;
    for (int i = tid; i < 2048; i += 128) {
        int ee = i>>5, j = i&31;
        wihT[j*128+ee]    = wihf[i];
        wihT[j*128+64+ee] = wihb[i];
    }
    for (int i = tid; i < 1024; i += 128) {
        int ee = i>>4, j = i&15;
        whhT[j*128+ee]    = whhf[i];
        whhT[j*128+64+ee] = whhb[i];
    }
    if (tid < 64) { bias[tid] = bihf[tid]+bhhf[tid]; bias[64+tid] = bihb[tid]+bhhb[tid]; }
    for (int i = tid; i < 3840; i += 128) sx[i] = g_hm[(size_t)s*3840 + i];
    if (tid < 32) sh[tid] = 0.f;
    __syncthreads();

    float c = 0.f;
    for (int t = 0; t < 120; t++) {
        int tt = dir ? (119-t) : t;
        const float* xr = sx + tt*32;
        float a0=0.f, a1=0.f, a2=0.f, a3=0.f;
        #pragma unroll
        for (int j = 0; j < 32; j += 4) {
            a0 = fmaf(xr[j+0], wihT[(j+0)*128+tid], a0);
            a1 = fmaf(xr[j+1], wihT[(j+1)*128+tid], a1);
            a2 = fmaf(xr[j+2], wihT[(j+2)*128+tid], a2);
            a3 = fmaf(xr[j+3], wihT[(j+3)*128+tid], a3);
        }
        const float* hp = sh + dir*16;
        #pragma unroll
        for (int j = 0; j < 16; j += 4) {
            a0 = fmaf(hp[j+0], whhT[(j+0)*128+tid], a0);
            a1 = fmaf(hp[j+1], whhT[(j+1)*128+tid], a1);
            a2 = fmaf(hp[j+2], whhT[(j+2)*128+tid], a2);
            a3 = fmaf(hp[j+3], whhT[(j+3)*128+tid], a3);
        }
        sgt[tid] = bias[tid] + (a0+a1) + (a2+a3);
        __syncthreads();
        if (e < 16) {
            float gi = sgt[dir*64+e], gf = sgt[dir*64+16+e], gg = sgt[dir*64+32+e], go = sgt[dir*64+48+e];
            c = fsig(gf)*c + fsig(gi)*ftanh(gg);
            float h = fsig(go)*ftanh(c);
            sh[dir*16+e] = h;
            g_hcat[((size_t)s*120+tt)*32 + dir*16 + e] = h;
        }
        __syncthreads();
    }
}

__global__ void k_lin(const float* __restrict__ lw, const float* __restrict__ lb,
                      float* __restrict__ out)
{
    int i = blockIdx.x*256 + threadIdx.x;
    if (i < 7680) {
        int bt = i>>1, o = i&1;
        const float* h = g_hcat + (size_t)bt*32;
        float acc = lb[o];
        #pragma unroll
        for (int k = 0; k < 32; k++) acc += h[k]*lw[o*32+k];
        out[i] = acc;
    }
}

extern "C" void kernel_launch(void* const* d_in, const int* in_sizes, int n_in,
                              void* d_out, int out_size)
{
    const float* x    = (const float*)d_in[0];
    const float* pos  = (const float*)d_in[1];
    const float* c1w  = (const float*)d_in[2];
    const float* c1b  = (const float*)d_in[3];
    const float* c2w  = (const float*)d_in[4];
    const float* c2b  = (const float*)d_in[5];
    const float* wq   = (const float*)d_in[6];
    const float* bq   = (const float*)d_in[7];
    const float* wk   = (const float*)d_in[8];
    const float* bk   = (const float*)d_in[9];
    const float* wv   = (const float*)d_in[10];
    const float* bv   = (const float*)d_in[11];
    const float* wo   = (const float*)d_in[12];
    const float* bo   = (const float*)d_in[13];
    const float* ln1g = (const float*)d_in[14];
    const float* ln1b = (const float*)d_in[15];
    const float* w1   = (const float*)d_in[16];
    const float* b1   = (const float*)d_in[17];
    const float* w2   = (const float*)d_in[18];
    const float* b2   = (const float*)d_in[19];
    const float* ln2g = (const float*)d_in[20];
    const float* ln2b = (const float*)d_in[21];
    const float* wihf = (const float*)d_in[22];
    const float* whhf = (const float*)d_in[23];
    const float* bihf = (const float*)d_in[24];
    const float* bhhf = (const float*)d_in[25];
    const float* wihb = (const float*)d_in[26];
    const float* whhb = (const float*)d_in[27];
    const float* bihb = (const float*)d_in[28];
    const float* bhhb = (const float*)d_in[29];
    const float* lw   = (const float*)d_in[30];
    const float* lb   = (const float*)d_in[31];
    float* out = (float*)d_out;

    cudaFuncSetAttribute(k_cnn,   cudaFuncAttributeMaxDynamicSharedMemorySize, 80*1024);
    cudaFuncSetAttribute(k_xform, cudaFuncAttributeMaxDynamicSharedMemorySize, 80*1024);
    cudaFuncSetAttribute(k_ffn,   cudaFuncAttributeMaxDynamicSharedMemorySize, 96*1024);

    k_cnn  <<<4560, 256, 74368>>>(x, c1w, c1b, c2w, c2b, pos);
    k_xform<<<960, 320, 74432>>>(wq, bq, wk, bk, wv, bv, wo, bo, ln1g, ln1b, pos);
    k_ffn  <<<960, 320, 87104>>>(w1, b1, w2, b2, ln2g, ln2b, out);
    k_lstm <<<32, 128>>>(wihf, whhf, bihf, bhhf, wihb, whhb, bihb, bhhb);
    k_lin  <<<30, 256>>>(lw, lb, out);
}

// round 5
// speedup vs baseline: 1.5728x; 1.0345x over previous
#include <cuda_runtime.h>
#include <math.h>

#define BT    3840
#define NROWS 76800

__device__ float g_tok [BT*19*32];
__device__ float g_tok2[NROWS*32];
__device__ float g_hm  [BT*32];
__device__ float g_hcat[BT*32];
__device__ float g_xg  [64*120*64];

__constant__ unsigned c_maskb[20] = {
    0x1Fu,0x73u,0x1DDu,0x33Du,0x23Bu,0x67Au,0xC76u,0x3984u,0x779Cu,0xE738u,
    0x1CF70u,0x18CC0u,0x33180u,0x2F380u,0x6E700u,0x5EE00u,0x59C00u,0x67000u,0x7C000u,0xFFFFFu
};

__device__ __forceinline__ unsigned long long pack2(float lo, float hi){
    unsigned long long r;
    asm("mov.b64 %0, {%1, %2};" : "=l"(r) : "f"(lo), "f"(hi));
    return r;
}
__device__ __forceinline__ void unpack2(unsigned long long v, float& lo, float& hi){
    asm("mov.b64 {%0, %1}, %2;" : "=f"(lo), "=f"(hi) : "l"(v));
}
__device__ __forceinline__ void ffma2(unsigned long long& d, unsigned long long a, unsigned long long b){
    asm("fma.rn.f32x2 %0, %1, %2, %0;" : "+l"(d) : "l"(a), "l"(b));
}
__device__ __forceinline__ float fsig(float x){ return __fdividef(1.f, 1.f + __expf(-x)); }
__device__ __forceinline__ float ftanh(float x){
    float ax = fabsf(x);
    float e  = __expf(2.f*ax);
    float t  = 1.f - __fdividef(2.f, e + 1.f);
    return (x < 0.f) ? -t : t;
}

// ---------------- CNN: warp = sample pair; conv2 via packed f32x2 FMA
__global__ __launch_bounds__(256) void k_cnn(
    const float* __restrict__ x, const float* __restrict__ c1w, const float* __restrict__ c1b,
    const float* __restrict__ c2w, const float* __restrict__ c2b, const float* __restrict__ pos)
{
    extern __shared__ __align__(16) float sm[];
    float* w2s = sm;              // 5120
    float* b2s = sm + 5120;       // 32
    float* sx  = sm + 5152;       // 3200
    float* h1p = sm + 8352;       // 8*1280

    int tid = threadIdx.x, w = tid >> 5, oc = tid & 31;
    int n0 = blockIdx.x * 16;

    for (int i = tid; i < 5120; i += 256) {
        int o = i/160, r = i - o*160, ic = r/5, k = r - ic*5;
        w2s[(ic*5+k)*32 + o] = c2w[i];
    }
    if (tid < 32) b2s[tid] = c2b[tid];
    {
        const float4* xg = (const float4*)(x + (size_t)n0*200);
        float4* sx4 = (float4*)sx;
        for (int i = tid; i < 800; i += 256) sx4[i] = xg[i];
    }
    __syncthreads();

    float w1r[5];
    #pragma unroll
    for (int k = 0; k < 5; k++) w1r[k] = c1w[oc*5+k];
    float b1 = c1b[oc];
    float po[2][20];
    #pragma unroll
    for (int s = 0; s < 2; s++) {
        const float* xs = sx + (2*w+s)*200;
        #pragma unroll 4
        for (int j = 0; j < 20; j++) {
            float o0 = b1, o1 = b1;
            #pragma unroll
            for (int k = 0; k < 5; k++) { o0 += xs[10*j+k]*w1r[k]; o1 += xs[10*j+5+k]*w1r[k]; }
            po[s][j] = fmaxf(fmaxf(o0,0.f), fmaxf(o1,0.f));
        }
    }
    float* hw = h1p + w*1280;
    #pragma unroll
    for (int t = 0; t < 20; t += 2) {
        float4 v = make_float4(po[0][t], po[1][t], po[0][t+1], po[1][t+1]);
        *(float4*)(hw + (oc*20 + t)*2) = v;
    }
    __syncwarp();

    unsigned long long acc[8];
    #pragma unroll
    for (int j = 0; j < 8; j++) acc[j] = 0ULL;
    #pragma unroll 2
    for (int ic = 0; ic < 32; ic++) {
        const ulonglong2* pv = (const ulonglong2*)(hw + ic*40);
        unsigned long long pr[20];
        #pragma unroll
        for (int q = 0; q < 10; q++) { ulonglong2 u = pv[q]; pr[2*q] = u.x; pr[2*q+1] = u.y; }
        unsigned long long wp[5];
        #pragma unroll
        for (int k = 0; k < 5; k++) { float wv_ = w2s[(ic*5+k)*32+oc]; wp[k] = pack2(wv_, wv_); }
        #pragma unroll
        for (int j = 0; j < 8; j++) {
            #pragma unroll
            for (int k = 0; k < 5; k++) ffma2(acc[j], pr[2*j+k], wp[k]);
        }
    }
    float aA[8], aB[8];
    #pragma unroll
    for (int j = 0; j < 8; j++) unpack2(acc[j], aA[j], aB[j]);
    float b2r = b2s[oc];
    #pragma unroll
    for (int s = 0; s < 2; s++) {
        const float* a = s ? aB : aA;
        float v = 0.f;
        #pragma unroll
        for (int u = 0; u < 4; u++)
            v += fmaxf(fmaxf(a[2*u]+b2r, 0.f), fmaxf(a[2*u+1]+b2r, 0.f));
        int n = n0 + 2*w + s, c = n % 19;
        g_tok[(size_t)n*32 + oc] = 0.25f*v + pos[c*32+oc];
    }
}

// ---------------- fused QKV + attention + proj + LN1 ; 4 samples/block, 320 thr
__global__ __launch_bounds__(320) void k_xform(
    const float* __restrict__ wq, const float* __restrict__ bq,
    const float* __restrict__ wk, const float* __restrict__ bk,
    const float* __restrict__ wv, const float* __restrict__ bv,
    const float* __restrict__ wo, const float* __restrict__ bo,
    const float* __restrict__ g1, const float* __restrict__ be1,
    const float* __restrict__ pos)
{
    extern __shared__ __align__(16) float sm[];
    float* WT   = sm;            // 3072
    float* sbq  = sm + 3072;     // 96
    float* WOT  = sm + 3168;     // 1024
    float* sbo  = sm + 4192;     // 32
    float* sg   = sm + 4224;     // 32
    float* sbe  = sm + 4256;     // 32
    float* As   = sm + 4288;     // 80*33
    float* QKV  = sm + 6928;     // 4*2160
    float* Os   = sm + 15568;    // 80*36
    float* smu  = sm + 18448;    // 80
    float* srs  = sm + 18528;    // 80

    int tid = threadIdx.x;
    int s0 = blockIdx.x * 4;

    for (int i = tid; i < 3072; i += 320) {
        int j = i/96, n = i%96;
        WT[i] = (n<32) ? wq[n*32+j] : (n<64) ? wk[(n-32)*32+j] : wv[(n-64)*32+j];
    }
    for (int i = tid; i < 96; i += 320) sbq[i] = (i<32)?bq[i]:(i<64)?bk[i-32]:bv[i-64];
    for (int i = tid; i < 1024; i += 320) { int d = i>>5, j = i&31; WOT[j*32+d] = wo[i]; }
    if (tid < 32) { sbo[tid]=bo[tid]; sg[tid]=g1[tid]; sbe[tid]=be1[tid]; }
    for (int i = tid; i < 640; i += 320) {
        int rr = i>>3, d4 = (i&7)*4;
        int sl = rr/20, t = rr - sl*20;
        const float4 v = (t < 19)
            ? *(const float4*)(g_tok + ((size_t)(s0+sl)*19 + t)*32 + d4)
            : *(const float4*)(pos + 19*32 + d4);
        float* d = As + rr*33 + d4;
        d[0]=v.x; d[1]=v.y; d[2]=v.z; d[3]=v.w;
    }
    __syncthreads();

    {
        int rowg = tid>>3, colg = tid&7;
        float acc0[12], acc1[12];
        #pragma unroll
        for (int c = 0; c < 12; c++) { acc0[c]=0.f; acc1[c]=0.f; }
        #pragma unroll 8
        for (int j = 0; j < 32; j++) {
            float a0 = As[(2*rowg)*33+j], a1 = As[(2*rowg+1)*33+j];
            const float4* wp4 = (const float4*)(WT + j*96 + colg*12);
            float4 wv4[3]; wv4[0]=wp4[0]; wv4[1]=wp4[1]; wv4[2]=wp4[2];
            const float* wr = (const float*)wv4;
            #pragma unroll
            for (int c = 0; c < 12; c++) { float ww = wr[c]; acc0[c] += a0*ww; acc1[c] += a1*ww; }
        }
        #pragma unroll
        for (int c = 0; c < 12; c++) {
            int n = colg*12 + c;
            int which = n>>5, d = n&31;
            float b = sbq[n];
            int rr0 = 2*rowg, rr1 = rr0+1;
            int sl0 = rr0/20, t0 = rr0 - sl0*20;
            int sl1 = rr1/20, t1 = rr1 - sl1*20;
            QKV[sl0*2160 + which*720 + t0*36 + d] = acc0[c] + b;
            QKV[sl1*2160 + which*720 + t1*36 + d] = acc1[c] + b;
        }
    }
    __syncthreads();

    #pragma unroll
    for (int pass = 0; pass < 2; pass++) {
        int hi = (tid >= 160);
        int sl = pass*2 + hi;
        int slot = tid - hi*160;
        int t = slot>>3, h = slot&7;
        const float* qs = QKV + sl*2160;
        const float* ks = qs + 720;
        const float* vs = qs + 1440;
        float4 q4 = *(const float4*)(qs + t*36 + h*4);
        unsigned mb = c_maskb[t];
        float sc[20], mx = -1e30f;
        #pragma unroll
        for (int kt = 0; kt < 20; kt++) {
            float4 k4 = *(const float4*)(ks + kt*36 + h*4);
            float s = 0.5f*(q4.x*k4.x+q4.y*k4.y+q4.z*k4.z+q4.w*k4.w);
            if (!((mb>>kt)&1u)) s = -1e9f;
            sc[kt] = s; mx = fmaxf(mx, s);
        }
        float sum = 0.f;
        #pragma unroll
        for (int kt = 0; kt < 20; kt++) { sc[kt] = __expf(sc[kt]-mx); sum += sc[kt]; }
        float inv = __fdividef(1.f, sum);
        float4 o = make_float4(0.f,0.f,0.f,0.f);
        #pragma unroll
        for (int kt = 0; kt < 20; kt++) {
            float a = sc[kt];
            float4 v4 = *(const float4*)(vs + kt*36 + h*4);
            o.x += a*v4.x; o.y += a*v4.y; o.z += a*v4.z; o.w += a*v4.w;
        }
        o.x *= inv; o.y *= inv; o.z *= inv; o.w *= inv;
        *(float4*)(Os + (sl*20 + t)*36 + h*4) = o;
    }
    __syncthreads();

    float* Ps = QKV;
    {
        int rowg = tid>>3, colg = tid&7;
        float4 a0 = make_float4(0,0,0,0), a1 = make_float4(0,0,0,0);
        #pragma unroll 8
        for (int j = 0; j < 32; j++) {
            float4 w4 = *(const float4*)(WOT + j*32 + colg*4);
            float x0 = Os[(2*rowg)*36+j], x1 = Os[(2*rowg+1)*36+j];
            a0.x += x0*w4.x; a0.y += x0*w4.y; a0.z += x0*w4.z; a0.w += x0*w4.w;
            a1.x += x1*w4.x; a1.y += x1*w4.y; a1.z += x1*w4.z; a1.w += x1*w4.w;
        }
        #pragma unroll
        for (int i = 0; i < 2; i++) {
            int rr = 2*rowg + i;
            const float* res = As + rr*33 + colg*4;
            float4 ac = i ? a1 : a0;
            float* d = Ps + rr*33 + colg*4;
            d[0]=ac.x+sbo[colg*4+0]+res[0];
            d[1]=ac.y+sbo[colg*4+1]+res[1];
            d[2]=ac.z+sbo[colg*4+2]+res[2];
            d[3]=ac.w+sbo[colg*4+3]+res[3];
        }
    }
    __syncthreads();
    if (tid < 80) {
        const float* row = Ps + tid*33;
        float mu = 0.f;
        #pragma unroll
        for (int j = 0; j < 32; j++) mu += row[j];
        mu *= 0.03125f;
        float var = 0.f;
        #pragma unroll
        for (int j = 0; j < 32; j++) { float dd = row[j]-mu; var += dd*dd; }
        smu[tid] = mu; srs[tid] = rsqrtf(var*0.03125f + 1e-5f);
    }
    __syncthreads();
    size_t base = (size_t)blockIdx.x * 80 * 32;
    for (int i = tid; i < 2560; i += 320) {
        int rr = i>>5, d = i&31;
        g_tok2[base + i] = (Ps[rr*33+d]-smu[rr])*srs[rr]*sg[d] + sbe[d];
    }
}

// ---------------- fused FF1+ReLU+FF2+residual+LN2 + split write ; 4 samples/block
__global__ __launch_bounds__(320) void k_ffn(
    const float* __restrict__ w1, const float* __restrict__ b1,
    const float* __restrict__ w2, const float* __restrict__ b2,
    const float* __restrict__ g2, const float* __restrict__ be2,
    float* __restrict__ out)
{
    extern __shared__ __align__(16) float sm[];
    float* W1T = sm;             // 4096
    float* sb1 = sm + 4096;      // 128
    float* W2T = sm + 4224;      // 4096
    float* sb2 = sm + 8320;      // 32
    float* sg  = sm + 8352;      // 32
    float* sbe = sm + 8384;      // 32
    float* As  = sm + 8416;      // 80*33
    float* Hs  = sm + 11056;     // 80*132
    float* smu = sm + 21616;     // 80
    float* srs = sm + 21696;     // 80

    int tid = threadIdx.x;
    int s0 = blockIdx.x * 4;
    size_t base = (size_t)blockIdx.x * 80 * 32;

    for (int i = tid; i < 4096; i += 320) {
        { int f = i>>5, j = i&31;  W1T[j*128+f] = w1[i]; }
        { int d = i>>7, f = i&127; W2T[f*32+d]  = w2[i]; }
    }
    if (tid < 128) sb1[tid] = b1[tid];
    if (tid < 32) { sb2[tid]=b2[tid]; sg[tid]=g2[tid]; sbe[tid]=be2[tid]; }
    for (int i = tid; i < 2560; i += 320) As[(i>>5)*33+(i&31)] = g_tok2[base + i];
    __syncthreads();

    {
        int rowg = tid>>4, colg = tid&15;
        float acc[4][8];
        #pragma unroll
        for (int i = 0; i < 4; i++)
            #pragma unroll
            for (int c = 0; c < 8; c++) acc[i][c] = 0.f;
        #pragma unroll 4
        for (int j = 0; j < 32; j++) {
            const float4* wp4 = (const float4*)(W1T + j*128 + colg*8);
            float4 wa = wp4[0], wb = wp4[1];
            float wr[8] = {wa.x,wa.y,wa.z,wa.w, wb.x,wb.y,wb.z,wb.w};
            #pragma unroll
            for (int i = 0; i < 4; i++) {
                float a = As[(4*rowg+i)*33+j];
                #pragma unroll
                for (int c = 0; c < 8; c++) acc[i][c] += a*wr[c];
            }
        }
        #pragma unroll
        for (int i = 0; i < 4; i++)
            #pragma unroll
            for (int c = 0; c < 8; c++)
                Hs[(4*rowg+i)*132 + colg*8+c] = fmaxf(acc[i][c]+sb1[colg*8+c], 0.f);
    }
    __syncthreads();

    int rowg = tid>>3, colg = tid&7;
    float4 v0, v1;
    {
        float4 a0 = make_float4(0,0,0,0), a1 = make_float4(0,0,0,0);
        #pragma unroll 8
        for (int f = 0; f < 128; f++) {
            float4 w4 = *(const float4*)(W2T + f*32 + colg*4);
            float h0 = Hs[(2*rowg)*132+f], h1 = Hs[(2*rowg+1)*132+f];
            a0.x += h0*w4.x; a0.y += h0*w4.y; a0.z += h0*w4.z; a0.w += h0*w4.w;
            a1.x += h1*w4.x; a1.y += h1*w4.y; a1.z += h1*w4.z; a1.w += h1*w4.w;
        }
        const float* r0 = As + (2*rowg)*33 + colg*4;
        const float* r1 = As + (2*rowg+1)*33 + colg*4;
        v0 = make_float4(a0.x+sb2[colg*4+0]+r0[0], a0.y+sb2[colg*4+1]+r0[1],
                         a0.z+sb2[colg*4+2]+r0[2], a0.w+sb2[colg*4+3]+r0[3]);
        v1 = make_float4(a1.x+sb2[colg*4+0]+r1[0], a1.y+sb2[colg*4+1]+r1[1],
                         a1.z+sb2[colg*4+2]+r1[2], a1.w+sb2[colg*4+3]+r1[3]);
    }
    __syncthreads();
    float* Ps = Hs;
    { float* d = Ps + (2*rowg)*33 + colg*4;   d[0]=v0.x; d[1]=v0.y; d[2]=v0.z; d[3]=v0.w; }
    { float* d = Ps + (2*rowg+1)*33 + colg*4; d[0]=v1.x; d[1]=v1.y; d[2]=v1.z; d[3]=v1.w; }
    __syncthreads();
    if (tid < 80) {
        const float* row = Ps + tid*33;
        float mu = 0.f;
        #pragma unroll
        for (int j = 0; j < 32; j++) mu += row[j];
        mu *= 0.03125f;
        float var = 0.f;
        #pragma unroll
        for (int j = 0; j < 32; j++) { float dd = row[j]-mu; var += dd*dd; }
        smu[tid] = mu; srs[tid] = rsqrtf(var*0.03125f + 1e-5f);
    }
    __syncthreads();
    for (int i = tid; i < 2560; i += 320) {
        int rr = i>>5, d = i&31;
        float o = (Ps[rr*33+d]-smu[rr])*srs[rr]*sg[d] + sbe[d];
        int sl = rr/20, t = rr - sl*20;
        int bt = s0 + sl;
        if (t < 19) out[7680 + (size_t)bt*608 + t*32 + d] = o;
        else        g_hm[(size_t)bt*32 + d] = o;
    }
}

// ---------------- LSTM x-gate precompute: xg[sd][t][g] = bih+bhh + x_t @ wih^T
__global__ __launch_bounds__(256) void k_gates(
    const float* __restrict__ wihf, const float* __restrict__ bihf, const float* __restrict__ bhhf,
    const float* __restrict__ wihb, const float* __restrict__ bihb, const float* __restrict__ bhhb)
{
    __shared__ __align__(16) float sx[3840];
    int tid = threadIdx.x;
    int sd = blockIdx.x, s = sd >> 1, dir = sd & 1;
    const float* wih = dir ? wihb : wihf;
    const float* bih = dir ? bihb : bihf;
    const float* bhh = dir ? bhhb : bhhf;
    int g = tid & 63, tgrp = tid >> 6;
    for (int i = tid; i < 3840; i += 256) sx[i] = g_hm[(size_t)s*3840 + i];
    float wr[32];
    #pragma unroll
    for (int j = 0; j < 32; j++) wr[j] = wih[g*32+j];
    float b = bih[g] + bhh[g];
    __syncthreads();
    for (int t = tgrp; t < 120; t += 4) {
        const float* xr = sx + t*32;
        float a0=b, a1=0.f, a2=0.f, a3=0.f;
        #pragma unroll
        for (int j = 0; j < 32; j += 4) {
            a0 = fmaf(xr[j+0], wr[j+0], a0);
            a1 = fmaf(xr[j+1], wr[j+1], a1);
            a2 = fmaf(xr[j+2], wr[j+2], a2);
            a3 = fmaf(xr[j+3], wr[j+3], a3);
        }
        g_xg[((size_t)sd*120 + t)*64 + g] = (a0+a1) + (a2+a3);
    }
}

// ---------------- LSTM recurrence: 1 warp per (seq, dir); no block barriers
__global__ __launch_bounds__(32) void k_lstm2(
    const float* __restrict__ whhf, const float* __restrict__ whhb)
{
    __shared__ __align__(16) float sxg[7680];
    __shared__ float sh[16];
    int l = threadIdx.x;
    int sd = blockIdx.x, s = sd >> 1, dir = sd & 1;
    const float* whh = dir ? whhb : whhf;
    float w0[16], w1[16];
    #pragma unroll
    for (int j = 0; j < 16; j++) { w0[j] = whh[l*16+j]; w1[j] = whh[(l+32)*16+j]; }
    {
        const float4* xg4 = (const float4*)(g_xg + (size_t)sd*7680);
        float4* s4 = (float4*)sxg;
        for (int i = l; i < 1920; i += 32) s4[i] = xg4[i];
    }
    if (l < 16) sh[l] = 0.f;
    __syncwarp();

    float c = 0.f;
    for (int t = 0; t < 120; t++) {
        int tt = dir ? (119-t) : t;
        const float* xr = sxg + tt*64;
        float g0 = xr[l], g1 = xr[l+32];
        float g0a=0.f, g0b=0.f, g1a=0.f, g1b=0.f;
        #pragma unroll
        for (int j = 0; j < 16; j += 2) {
            float h0 = sh[j], h1 = sh[j+1];
            g0a = fmaf(h0, w0[j],   g0a);
            g0b = fmaf(h1, w0[j+1], g0b);
            g1a = fmaf(h0, w1[j],   g1a);
            g1b = fmaf(h1, w1[j+1], g1b);
        }
        g0 += g0a + g0b;   // lane<16: i gate ; lane>=16: f gate
        g1 += g1a + g1b;   // lane<16: g gate ; lane>=16: o gate
        float fg = __shfl_sync(0xffffffffu, g0, l+16);
        float og = __shfl_sync(0xffffffffu, g1, l+16);
        if (l < 16) {
            c = fsig(fg)*c + fsig(g0)*ftanh(g1);
            float h = fsig(og)*ftanh(c);
            sh[l] = h;
            g_hcat[((size_t)s*120 + tt)*32 + dir*16 + l] = h;
        }
        __syncwarp();
    }
}

__global__ void k_lin(const float* __restrict__ lw, const float* __restrict__ lb,
                      float* __restrict__ out)
{
    int i = blockIdx.x*256 + threadIdx.x;
    if (i < 7680) {
        int bt = i>>1, o = i&1;
        const float* h = g_hcat + (size_t)bt*32;
        float acc = lb[o];
        #pragma unroll
        for (int k = 0; k < 32; k++) acc += h[k]*lw[o*32+k];
        out[i] = acc;
    }
}

extern "C" void kernel_launch(void* const* d_in, const int* in_sizes, int n_in,
                              void* d_out, int out_size)
{
    const float* x    = (const float*)d_in[0];
    const float* pos  = (const float*)d_in[1];
    const float* c1w  = (const float*)d_in[2];
    const float* c1b  = (const float*)d_in[3];
    const float* c2w  = (const float*)d_in[4];
    const float* c2b  = (const float*)d_in[5];
    const float* wq   = (const float*)d_in[6];
    const float* bq   = (const float*)d_in[7];
    const float* wk   = (const float*)d_in[8];
    const float* bk   = (const float*)d_in[9];
    const float* wv   = (const float*)d_in[10];
    const float* bv   = (const float*)d_in[11];
    const float* wo   = (const float*)d_in[12];
    const float* bo   = (const float*)d_in[13];
    const float* ln1g = (const float*)d_in[14];
    const float* ln1b = (const float*)d_in[15];
    const float* w1   = (const float*)d_in[16];
    const float* b1   = (const float*)d_in[17];
    const float* w2   = (const float*)d_in[18];
    const float* b2   = (const float*)d_in[19];
    const float* ln2g = (const float*)d_in[20];
    const float* ln2b = (const float*)d_in[21];
    const float* wihf = (const float*)d_in[22];
    const float* whhf = (const float*)d_in[23];
    const float* bihf = (const float*)d_in[24];
    const float* bhhf = (const float*)d_in[25];
    const float* wihb = (const float*)d_in[26];
    const float* whhb = (const float*)d_in[27];
    const float* bihb = (const float*)d_in[28];
    const float* bhhb = (const float*)d_in[29];
    const float* lw   = (const float*)d_in[30];
    const float* lb   = (const float*)d_in[31];
    float* out = (float*)d_out;

    cudaFuncSetAttribute(k_cnn,   cudaFuncAttributeMaxDynamicSharedMemorySize, 80*1024);
    cudaFuncSetAttribute(k_xform, cudaFuncAttributeMaxDynamicSharedMemorySize, 80*1024);
    cudaFuncSetAttribute(k_ffn,   cudaFuncAttributeMaxDynamicSharedMemorySize, 96*1024);

    k_cnn  <<<4560, 256, 74368>>>(x, c1w, c1b, c2w, c2b, pos);
    k_xform<<<960, 320, 74432>>>(wq, bq, wk, bk, wv, bv, wo, bo, ln1g, ln1b, pos);
    k_ffn  <<<960, 320, 87104>>>(w1, b1, w2, b2, ln2g, ln2b, out);
    k_gates<<<64, 256>>>(wihf, bihf, bhhf, wihb, bihb, bhhb);
    k_lstm2<<<64, 32>>>(whhf, whhb);
    k_lin  <<<30, 256>>>(lw, lb, out);
}

// round 6
// speedup vs baseline: 1.6125x; 1.0253x over previous
#include <cuda_runtime.h>
#include <math.h>

#define BT    3840
#define NROWS 76800

__device__ float g_tok [BT*19*32];
__device__ float g_tok2[NROWS*32];
__device__ float g_hm  [BT*32];
__device__ float g_hcat[BT*32];
__device__ float g_xg  [64*120*64];

__constant__ unsigned c_maskb[20] = {
    0x1Fu,0x73u,0x1DDu,0x33Du,0x23Bu,0x67Au,0xC76u,0x3984u,0x779Cu,0xE738u,
    0x1CF70u,0x18CC0u,0x33180u,0x2F380u,0x6E700u,0x5EE00u,0x59C00u,0x67000u,0x7C000u,0xFFFFFu
};

__device__ __forceinline__ unsigned long long pack2(float lo, float hi){
    unsigned long long r;
    asm("mov.b64 %0, {%1, %2};" : "=l"(r) : "f"(lo), "f"(hi));
    return r;
}
__device__ __forceinline__ void unpack2(unsigned long long v, float& lo, float& hi){
    asm("mov.b64 {%0, %1}, %2;" : "=f"(lo), "=f"(hi) : "l"(v));
}
__device__ __forceinline__ void ffma2(unsigned long long& d, unsigned long long a, unsigned long long b){
    asm("fma.rn.f32x2 %0, %1, %2, %0;" : "+l"(d) : "l"(a), "l"(b));
}
__device__ __forceinline__ float fsig(float x){ return __fdividef(1.f, 1.f + __expf(-x)); }
__device__ __forceinline__ float ftanh(float x){
    float ax = fabsf(x);
    float e  = __expf(2.f*ax);
    float t  = 1.f - __fdividef(2.f, e + 1.f);
    return (x < 0.f) ? -t : t;
}

// ---------------- CNN: warp = sample pair; conv2 via packed f32x2 FMA
// smem: w2s | b2s | union{ sx (phase1) , h1p (phase2) }  => 61.6 KB, 3 blocks/SM
__global__ __launch_bounds__(256, 3) void k_cnn(
    const float* __restrict__ x, const float* __restrict__ c1w, const float* __restrict__ c1b,
    const float* __restrict__ c2w, const float* __restrict__ c2b, const float* __restrict__ pos)
{
    extern __shared__ __align__(16) float sm[];
    float* w2s = sm;              // 5120
    float* b2s = sm + 5120;       // 32
    float* uni = sm + 5152;       // union: sx[3200] then h1p[10240]
    float* sx  = uni;
    float* h1p = uni;

    int tid = threadIdx.x, w = tid >> 5, oc = tid & 31;
    int n0 = blockIdx.x * 16;

    for (int i = tid; i < 5120; i += 256) {
        int o = i/160, r = i - o*160, ic = r/5, k = r - ic*5;
        w2s[(ic*5+k)*32 + o] = c2w[i];
    }
    if (tid < 32) b2s[tid] = c2b[tid];
    {
        const float4* xg = (const float4*)(x + (size_t)n0*200);
        float4* sx4 = (float4*)sx;
        for (int i = tid; i < 800; i += 256) sx4[i] = xg[i];
    }
    __syncthreads();

    // ---- phase 1: conv1(s5)+relu+pool2, results kept in registers
    float w1r[5];
    #pragma unroll
    for (int k = 0; k < 5; k++) w1r[k] = c1w[oc*5+k];
    float b1 = c1b[oc];
    float po[2][20];
    #pragma unroll
    for (int s = 0; s < 2; s++) {
        const float* xs = sx + (2*w+s)*200;
        #pragma unroll 4
        for (int j = 0; j < 20; j++) {
            float o0 = b1, o1 = b1;
            #pragma unroll
            for (int k = 0; k < 5; k++) { o0 += xs[10*j+k]*w1r[k]; o1 += xs[10*j+5+k]*w1r[k]; }
            po[s][j] = fmaxf(fmaxf(o0,0.f), fmaxf(o1,0.f));
        }
    }
    __syncthreads();   // all sx reads done; safe to overwrite with h1p

    float* hw = h1p + w*1280;
    #pragma unroll
    for (int t = 0; t < 20; t += 2) {
        float4 v = make_float4(po[0][t], po[1][t], po[0][t+1], po[1][t+1]);
        *(float4*)(hw + (oc*20 + t)*2) = v;
    }
    __syncwarp();      // h1p region is warp-private

    unsigned long long acc[8];
    #pragma unroll
    for (int j = 0; j < 8; j++) acc[j] = 0ULL;
    #pragma unroll 2
    for (int ic = 0; ic < 32; ic++) {
        const ulonglong2* pv = (const ulonglong2*)(hw + ic*40);
        unsigned long long pr[20];
        #pragma unroll
        for (int q = 0; q < 10; q++) { ulonglong2 u = pv[q]; pr[2*q] = u.x; pr[2*q+1] = u.y; }
        unsigned long long wp[5];
        #pragma unroll
        for (int k = 0; k < 5; k++) { float wv_ = w2s[(ic*5+k)*32+oc]; wp[k] = pack2(wv_, wv_); }
        #pragma unroll
        for (int j = 0; j < 8; j++) {
            #pragma unroll
            for (int k = 0; k < 5; k++) ffma2(acc[j], pr[2*j+k], wp[k]);
        }
    }
    float aA[8], aB[8];
    #pragma unroll
    for (int j = 0; j < 8; j++) unpack2(acc[j], aA[j], aB[j]);
    float b2r = b2s[oc];
    #pragma unroll
    for (int s = 0; s < 2; s++) {
        const float* a = s ? aB : aA;
        float v = 0.f;
        #pragma unroll
        for (int u = 0; u < 4; u++)
            v += fmaxf(fmaxf(a[2*u]+b2r, 0.f), fmaxf(a[2*u+1]+b2r, 0.f));
        int n = n0 + 2*w + s, c = n % 19;
        g_tok[(size_t)n*32 + oc] = 0.25f*v + pos[c*32+oc];
    }
}

// ---------------- fused QKV + attention + proj + LN1 ; 4 samples/block, 320 thr
__global__ __launch_bounds__(320) void k_xform(
    const float* __restrict__ wq, const float* __restrict__ bq,
    const float* __restrict__ wk, const float* __restrict__ bk,
    const float* __restrict__ wv, const float* __restrict__ bv,
    const float* __restrict__ wo, const float* __restrict__ bo,
    const float* __restrict__ g1, const float* __restrict__ be1,
    const float* __restrict__ pos)
{
    extern __shared__ __align__(16) float sm[];
    float* WT   = sm;            // 3072
    float* sbq  = sm + 3072;     // 96
    float* WOT  = sm + 3168;     // 1024
    float* sbo  = sm + 4192;     // 32
    float* sg   = sm + 4224;     // 32
    float* sbe  = sm + 4256;     // 32
    float* As   = sm + 4288;     // 80*33
    float* QKV  = sm + 6928;     // 4*2160
    float* Os   = sm + 15568;    // 80*36
    float* smu  = sm + 18448;    // 80
    float* srs  = sm + 18528;    // 80

    int tid = threadIdx.x;
    int s0 = blockIdx.x * 4;

    for (int i = tid; i < 3072; i += 320) {
        int j = i/96, n = i%96;
        WT[i] = (n<32) ? wq[n*32+j] : (n<64) ? wk[(n-32)*32+j] : wv[(n-64)*32+j];
    }
    for (int i = tid; i < 96; i += 320) sbq[i] = (i<32)?bq[i]:(i<64)?bk[i-32]:bv[i-64];
    for (int i = tid; i < 1024; i += 320) { int d = i>>5, j = i&31; WOT[j*32+d] = wo[i]; }
    if (tid < 32) { sbo[tid]=bo[tid]; sg[tid]=g1[tid]; sbe[tid]=be1[tid]; }
    for (int i = tid; i < 640; i += 320) {
        int rr = i>>3, d4 = (i&7)*4;
        int sl = rr/20, t = rr - sl*20;
        const float4 v = (t < 19)
            ? *(const float4*)(g_tok + ((size_t)(s0+sl)*19 + t)*32 + d4)
            : *(const float4*)(pos + 19*32 + d4);
        float* d = As + rr*33 + d4;
        d[0]=v.x; d[1]=v.y; d[2]=v.z; d[3]=v.w;
    }
    __syncthreads();

    {
        int rowg = tid>>3, colg = tid&7;
        float acc0[12], acc1[12];
        #pragma unroll
        for (int c = 0; c < 12; c++) { acc0[c]=0.f; acc1[c]=0.f; }
        #pragma unroll 8
        for (int j = 0; j < 32; j++) {
            float a0 = As[(2*rowg)*33+j], a1 = As[(2*rowg+1)*33+j];
            const float4* wp4 = (const float4*)(WT + j*96 + colg*12);
            float4 wv4[3]; wv4[0]=wp4[0]; wv4[1]=wp4[1]; wv4[2]=wp4[2];
            const float* wr = (const float*)wv4;
            #pragma unroll
            for (int c = 0; c < 12; c++) { float ww = wr[c]; acc0[c] += a0*ww; acc1[c] += a1*ww; }
        }
        #pragma unroll
        for (int c = 0; c < 12; c++) {
            int n = colg*12 + c;
            int which = n>>5, d = n&31;
            float b = sbq[n];
            int rr0 = 2*rowg, rr1 = rr0+1;
            int sl0 = rr0/20, t0 = rr0 - sl0*20;
            int sl1 = rr1/20, t1 = rr1 - sl1*20;
            QKV[sl0*2160 + which*720 + t0*36 + d] = acc0[c] + b;
            QKV[sl1*2160 + which*720 + t1*36 + d] = acc1[c] + b;
        }
    }
    __syncthreads();

    #pragma unroll
    for (int pass = 0; pass < 2; pass++) {
        int hi = (tid >= 160);
        int sl = pass*2 + hi;
        int slot = tid - hi*160;
        int t = slot>>3, h = slot&7;
        const float* qs = QKV + sl*2160;
        const float* ks = qs + 720;
        const float* vs = qs + 1440;
        float4 q4 = *(const float4*)(qs + t*36 + h*4);
        unsigned mb = c_maskb[t];
        float sc[20], mx = -1e30f;
        #pragma unroll
        for (int kt = 0; kt < 20; kt++) {
            float4 k4 = *(const float4*)(ks + kt*36 + h*4);
            float s = 0.5f*(q4.x*k4.x+q4.y*k4.y+q4.z*k4.z+q4.w*k4.w);
            if (!((mb>>kt)&1u)) s = -1e9f;
            sc[kt] = s; mx = fmaxf(mx, s);
        }
        float sum = 0.f;
        #pragma unroll
        for (int kt = 0; kt < 20; kt++) { sc[kt] = __expf(sc[kt]-mx); sum += sc[kt]; }
        float inv = __fdividef(1.f, sum);
        float4 o = make_float4(0.f,0.f,0.f,0.f);
        #pragma unroll
        for (int kt = 0; kt < 20; kt++) {
            float a = sc[kt];
            float4 v4 = *(const float4*)(vs + kt*36 + h*4);
            o.x += a*v4.x; o.y += a*v4.y; o.z += a*v4.z; o.w += a*v4.w;
        }
        o.x *= inv; o.y *= inv; o.z *= inv; o.w *= inv;
        *(float4*)(Os + (sl*20 + t)*36 + h*4) = o;
    }
    __syncthreads();

    float* Ps = QKV;
    {
        int rowg = tid>>3, colg = tid&7;
        float4 a0 = make_float4(0,0,0,0), a1 = make_float4(0,0,0,0);
        #pragma unroll 8
        for (int j = 0; j < 32; j++) {
            float4 w4 = *(const float4*)(WOT + j*32 + colg*4);
            float x0 = Os[(2*rowg)*36+j], x1 = Os[(2*rowg+1)*36+j];
            a0.x += x0*w4.x; a0.y += x0*w4.y; a0.z += x0*w4.z; a0.w += x0*w4.w;
            a1.x += x1*w4.x; a1.y += x1*w4.y; a1.z += x1*w4.z; a1.w += x1*w4.w;
        }
        #pragma unroll
        for (int i = 0; i < 2; i++) {
            int rr = 2*rowg + i;
            const float* res = As + rr*33 + colg*4;
            float4 ac = i ? a1 : a0;
            float* d = Ps + rr*33 + colg*4;
            d[0]=ac.x+sbo[colg*4+0]+res[0];
            d[1]=ac.y+sbo[colg*4+1]+res[1];
            d[2]=ac.z+sbo[colg*4+2]+res[2];
            d[3]=ac.w+sbo[colg*4+3]+res[3];
        }
    }
    __syncthreads();
    if (tid < 80) {
        const float* row = Ps + tid*33;
        float mu = 0.f;
        #pragma unroll
        for (int j = 0; j < 32; j++) mu += row[j];
        mu *= 0.03125f;
        float var = 0.f;
        #pragma unroll
        for (int j = 0; j < 32; j++) { float dd = row[j]-mu; var += dd*dd; }
        smu[tid] = mu; srs[tid] = rsqrtf(var*0.03125f + 1e-5f);
    }
    __syncthreads();
    size_t base = (size_t)blockIdx.x * 80 * 32;
    for (int i = tid; i < 2560; i += 320) {
        int rr = i>>5, d = i&31;
        g_tok2[base + i] = (Ps[rr*33+d]-smu[rr])*srs[rr]*sg[d] + sbe[d];
    }
}

// ---------------- fused FF1+ReLU+FF2+residual+LN2 + split write ; 4 samples/block
__global__ __launch_bounds__(320) void k_ffn(
    const float* __restrict__ w1, const float* __restrict__ b1,
    const float* __restrict__ w2, const float* __restrict__ b2,
    const float* __restrict__ g2, const float* __restrict__ be2,
    float* __restrict__ out)
{
    extern __shared__ __align__(16) float sm[];
    float* W1T = sm;             // 4096
    float* sb1 = sm + 4096;      // 128
    float* W2T = sm + 4224;      // 4096
    float* sb2 = sm + 8320;      // 32
    float* sg  = sm + 8352;      // 32
    float* sbe = sm + 8384;      // 32
    float* As  = sm + 8416;      // 80*33
    float* Hs  = sm + 11056;     // 80*132
    float* smu = sm + 21616;     // 80
    float* srs = sm + 21696;     // 80

    int tid = threadIdx.x;
    int s0 = blockIdx.x * 4;
    size_t base = (size_t)blockIdx.x * 80 * 32;

    for (int i = tid; i < 4096; i += 320) {
        { int f = i>>5, j = i&31;  W1T[j*128+f] = w1[i]; }
        { int d = i>>7, f = i&127; W2T[f*32+d]  = w2[i]; }
    }
    if (tid < 128) sb1[tid] = b1[tid];
    if (tid < 32) { sb2[tid]=b2[tid]; sg[tid]=g2[tid]; sbe[tid]=be2[tid]; }
    for (int i = tid; i < 2560; i += 320) As[(i>>5)*33+(i&31)] = g_tok2[base + i];
    __syncthreads();

    {
        int rowg = tid>>4, colg = tid&15;
        float acc[4][8];
        #pragma unroll
        for (int i = 0; i < 4; i++)
            #pragma unroll
            for (int c = 0; c < 8; c++) acc[i][c] = 0.f;
        #pragma unroll 4
        for (int j = 0; j < 32; j++) {
            const float4* wp4 = (const float4*)(W1T + j*128 + colg*8);
            float4 wa = wp4[0], wb = wp4[1];
            float wr[8] = {wa.x,wa.y,wa.z,wa.w, wb.x,wb.y,wb.z,wb.w};
            #pragma unroll
            for (int i = 0; i < 4; i++) {
                float a = As[(4*rowg+i)*33+j];
                #pragma unroll
                for (int c = 0; c < 8; c++) acc[i][c] += a*wr[c];
            }
        }
        #pragma unroll
        for (int i = 0; i < 4; i++)
            #pragma unroll
            for (int c = 0; c < 8; c++)
                Hs[(4*rowg+i)*132 + colg*8+c] = fmaxf(acc[i][c]+sb1[colg*8+c], 0.f);
    }
    __syncthreads();

    int rowg = tid>>3, colg = tid&7;
    float4 v0, v1;
    {
        float4 a0 = make_float4(0,0,0,0), a1 = make_float4(0,0,0,0);
        #pragma unroll 8
        for (int f = 0; f < 128; f++) {
            float4 w4 = *(const float4*)(W2T + f*32 + colg*4);
            float h0 = Hs[(2*rowg)*132+f], h1 = Hs[(2*rowg+1)*132+f];
            a0.x += h0*w4.x; a0.y += h0*w4.y; a0.z += h0*w4.z; a0.w += h0*w4.w;
            a1.x += h1*w4.x; a1.y += h1*w4.y; a1.z += h1*w4.z; a1.w += h1*w4.w;
        }
        const float* r0 = As + (2*rowg)*33 + colg*4;
        const float* r1 = As + (2*rowg+1)*33 + colg*4;
        v0 = make_float4(a0.x+sb2[colg*4+0]+r0[0], a0.y+sb2[colg*4+1]+r0[1],
                         a0.z+sb2[colg*4+2]+r0[2], a0.w+sb2[colg*4+3]+r0[3]);
        v1 = make_float4(a1.x+sb2[colg*4+0]+r1[0], a1.y+sb2[colg*4+1]+r1[1],
                         a1.z+sb2[colg*4+2]+r1[2], a1.w+sb2[colg*4+3]+r1[3]);
    }
    __syncthreads();
    float* Ps = Hs;
    { float* d = Ps + (2*rowg)*33 + colg*4;   d[0]=v0.x; d[1]=v0.y; d[2]=v0.z; d[3]=v0.w; }
    { float* d = Ps + (2*rowg+1)*33 + colg*4; d[0]=v1.x; d[1]=v1.y; d[2]=v1.z; d[3]=v1.w; }
    __syncthreads();
    if (tid < 80) {
        const float* row = Ps + tid*33;
        float mu = 0.f;
        #pragma unroll
        for (int j = 0; j < 32; j++) mu += row[j];
        mu *= 0.03125f;
        float var = 0.f;
        #pragma unroll
        for (int j = 0; j < 32; j++) { float dd = row[j]-mu; var += dd*dd; }
        smu[tid] = mu; srs[tid] = rsqrtf(var*0.03125f + 1e-5f);
    }
    __syncthreads();
    for (int i = tid; i < 2560; i += 320) {
        int rr = i>>5, d = i&31;
        float o = (Ps[rr*33+d]-smu[rr])*srs[rr]*sg[d] + sbe[d];
        int sl = rr/20, t = rr - sl*20;
        int bt = s0 + sl;
        if (t < 19) out[7680 + (size_t)bt*608 + t*32 + d] = o;
        else        g_hm[(size_t)bt*32 + d] = o;
    }
}

// ---------------- LSTM x-gate precompute (parallel): block = (sd, 24 t's), 384 thr
__global__ __launch_bounds__(384) void k_gates(
    const float* __restrict__ wihf, const float* __restrict__ bihf, const float* __restrict__ bhhf,
    const float* __restrict__ wihb, const float* __restrict__ bihb, const float* __restrict__ bhhb)
{
    __shared__ __align__(16) float swT[2048], sx[768], sb[64];
    int tid = threadIdx.x;
    int b = blockIdx.x;
    int sd = b / 5, q = b - sd*5;          // sd 0..63, q 0..4
    int s = sd >> 1, dir = sd & 1;
    const float* wih = dir ? wihb : wihf;
    const float* bih = dir ? bihb : bihf;
    const float* bhh = dir ? bhhb : bhhf;
    int t0 = q*24;

    for (int i = tid; i < 2048; i += 384) {
        int g = i >> 5, j = i & 31;
        swT[j*64 + g] = wih[i];
    }
    for (int i = tid; i < 768; i += 384) sx[i] = g_hm[(size_t)s*3840 + (t0)*32 + i];
    if (tid < 64) sb[tid] = bih[tid] + bhh[tid];
    __syncthreads();

    int g = tid & 63, tl = tid >> 6;       // tl 0..5
    float b0 = sb[g];
    #pragma unroll
    for (int i = 0; i < 4; i++) {
        int t = tl*4 + i;                  // 0..23
        const float* xr = sx + t*32;
        float a0=b0, a1=0.f, a2=0.f, a3=0.f;
        #pragma unroll
        for (int j = 0; j < 32; j += 4) {
            a0 = fmaf(xr[j+0], swT[(j+0)*64+g], a0);
            a1 = fmaf(xr[j+1], swT[(j+1)*64+g], a1);
            a2 = fmaf(xr[j+2], swT[(j+2)*64+g], a2);
            a3 = fmaf(xr[j+3], swT[(j+3)*64+g], a3);
        }
        g_xg[((size_t)sd*120 + t0 + t)*64 + g] = (a0+a1) + (a2+a3);
    }
}

// ---------------- LSTM recurrence: 1 warp per (seq, dir); no block barriers
__global__ __launch_bounds__(32) void k_lstm2(
    const float* __restrict__ whhf, const float* __restrict__ whhb)
{
    __shared__ __align__(16) float sxg[7680];
    __shared__ float sh[16];
    int l = threadIdx.x;
    int sd = blockIdx.x, s = sd >> 1, dir = sd & 1;
    const float* whh = dir ? whhb : whhf;
    float w0[16], w1[16];
    #pragma unroll
    for (int j = 0; j < 16; j++) { w0[j] = whh[l*16+j]; w1[j] = whh[(l+32)*16+j]; }
    {
        const float4* xg4 = (const float4*)(g_xg + (size_t)sd*7680);
        float4* s4 = (float4*)sxg;
        for (int i = l; i < 1920; i += 32) s4[i] = xg4[i];
    }
    if (l < 16) sh[l] = 0.f;
    __syncwarp();

    float c = 0.f;
    for (int t = 0; t < 120; t++) {
        int tt = dir ? (119-t) : t;
        const float* xr = sxg + tt*64;
        float g0 = xr[l], g1 = xr[l+32];
        float g0a=0.f, g0b=0.f, g1a=0.f, g1b=0.f;
        #pragma unroll
        for (int j = 0; j < 16; j += 2) {
            float h0 = sh[j], h1 = sh[j+1];
            g0a = fmaf(h0, w0[j],   g0a);
            g0b = fmaf(h1, w0[j+1], g0b);
            g1a = fmaf(h0, w1[j],   g1a);
            g1b = fmaf(h1, w1[j+1], g1b);
        }
        g0 += g0a + g0b;
        g1 += g1a + g1b;
        float fg = __shfl_sync(0xffffffffu, g0, l+16);
        float og = __shfl_sync(0xffffffffu, g1, l+16);
        if (l < 16) {
            c = fsig(fg)*c + fsig(g0)*ftanh(g1);
            float h = fsig(og)*ftanh(c);
            sh[l] = h;
            g_hcat[((size_t)s*120 + tt)*32 + dir*16 + l] = h;
        }
        __syncwarp();
    }
}

__global__ void k_lin(const float* __restrict__ lw, const float* __restrict__ lb,
                      float* __restrict__ out)
{
    int i = blockIdx.x*256 + threadIdx.x;
    if (i < 7680) {
        int bt = i>>1, o = i&1;
        const float* h = g_hcat + (size_t)bt*32;
        float acc = lb[o];
        #pragma unroll
        for (int k = 0; k < 32; k++) acc += h[k]*lw[o*32+k];
        out[i] = acc;
    }
}

extern "C" void kernel_launch(void* const* d_in, const int* in_sizes, int n_in,
                              void* d_out, int out_size)
{
    const float* x    = (const float*)d_in[0];
    const float* pos  = (const float*)d_in[1];
    const float* c1w  = (const float*)d_in[2];
    const float* c1b  = (const float*)d_in[3];
    const float* c2w  = (const float*)d_in[4];
    const float* c2b  = (const float*)d_in[5];
    const float* wq   = (const float*)d_in[6];
    const float* bq   = (const float*)d_in[7];
    const float* wk   = (const float*)d_in[8];
    const float* bk   = (const float*)d_in[9];
    const float* wv   = (const float*)d_in[10];
    const float* bv   = (const float*)d_in[11];
    const float* wo   = (const float*)d_in[12];
    const float* bo   = (const float*)d_in[13];
    const float* ln1g = (const float*)d_in[14];
    const float* ln1b = (const float*)d_in[15];
    const float* w1   = (const float*)d_in[16];
    const float* b1   = (const float*)d_in[17];
    const float* w2   = (const float*)d_in[18];
    const float* b2   = (const float*)d_in[19];
    const float* ln2g = (const float*)d_in[20];
    const float* ln2b = (const float*)d_in[21];
    const float* wihf = (const float*)d_in[22];
    const float* whhf = (const float*)d_in[23];
    const float* bihf = (const float*)d_in[24];
    const float* bhhf = (const float*)d_in[25];
    const float* wihb = (const float*)d_in[26];
    const float* whhb = (const float*)d_in[27];
    const float* bihb = (const float*)d_in[28];
    const float* bhhb = (const float*)d_in[29];
    const float* lw   = (const float*)d_in[30];
    const float* lb   = (const float*)d_in[31];
    float* out = (float*)d_out;

    cudaFuncSetAttribute(k_cnn,   cudaFuncAttributeMaxDynamicSharedMemorySize, 64*1024);
    cudaFuncSetAttribute(k_xform, cudaFuncAttributeMaxDynamicSharedMemorySize, 80*1024);
    cudaFuncSetAttribute(k_ffn,   cudaFuncAttributeMaxDynamicSharedMemorySize, 96*1024);

    k_cnn  <<<4560, 256, 61568>>>(x, c1w, c1b, c2w, c2b, pos);
    k_xform<<<960, 320, 74432>>>(wq, bq, wk, bk, wv, bv, wo, bo, ln1g, ln1b, pos);
    k_ffn  <<<960, 320, 87104>>>(w1, b1, w2, b2, ln2g, ln2b, out);
    k_gates<<<320, 384>>>(wihf, bihf, bhhf, wihb, bihb, bhhb);
    k_lstm2<<<64, 32>>>(whhf, whhb);
    k_lin  <<<30, 256>>>(lw, lb, out);
}